// round 5
// baseline (speedup 1.0000x reference)
#include <cuda_runtime.h>
#include <cuda_bf16.h>
#include <cstdint>

// Dims
#define NB 32
#define NS 512
#define NE 1024
#define NP 256
#define NH 8
#define NHS 4096      /* NH*NS */
#define NM 16384      /* NB*NS */
#define NKC 768       /* NP*3 conv reduction */

// Scratch (allowed: __device__ globals)
__device__ __align__(16) float g_proj[(size_t)NM * NP];         // 16 MB
__device__ __align__(16) float g_rc[(size_t)NM * NP];           // 16 MB  rep_conv fp32
__device__ __align__(16) __nv_bfloat16 g_rcH[(size_t)NM * NP];  // 8 MB rep_conv bf16 hi
__device__ __align__(16) __nv_bfloat16 g_rcL[(size_t)NM * NP];  // 8 MB rep_conv bf16 lo
__device__ __align__(16) __nv_bfloat16 g_BtH[(size_t)NHS * NP]; // 2 MB attn_w^T reordered hi
__device__ __align__(16) __nv_bfloat16 g_BtL[(size_t)NHS * NP]; // 2 MB lo
__device__ __align__(16) float g_A[(size_t)NB * NS * NS];       // 33.5 MB head-folded exp
__device__ __align__(16) float g_abr[NHS];                      // reordered attn_b
__device__ __align__(16) float g_Z[NM];                         // row sums
__device__ __align__(16) float g_wnum[NB * NS];                 // softmax-weight numerator
__device__ __align__(16) float g_Wc[NKC * NP];                  // transposed conv_w
__device__ __align__(16) float g_base[NS];                      // masked-row analytic contribution

// ================================================================ helpers
__device__ __forceinline__ uint32_t smem_to_u32(const void* p) {
    uint32_t a;
    asm("{ .reg .u64 t; cvta.to.shared.u64 t, %1; cvt.u32.u64 %0, t; }" : "=r"(a) : "l"(p));
    return a;
}
__device__ __forceinline__ void ldsm_x4(uint32_t* r, uint32_t addr) {
    asm volatile("ldmatrix.sync.aligned.m8n8.x4.shared.b16 {%0,%1,%2,%3}, [%4];"
                 : "=r"(r[0]), "=r"(r[1]), "=r"(r[2]), "=r"(r[3]) : "r"(addr));
}
__device__ __forceinline__ void mma_bf16(float* c, const uint32_t* a, const uint32_t* bb) {
    asm volatile(
        "mma.sync.aligned.m16n8k16.row.col.f32.bf16.bf16.f32 "
        "{%0,%1,%2,%3}, {%4,%5,%6,%7}, {%8,%9}, {%0,%1,%2,%3};"
        : "+f"(c[0]), "+f"(c[1]), "+f"(c[2]), "+f"(c[3])
        : "r"(a[0]), "r"(a[1]), "r"(a[2]), "r"(a[3]), "r"(bb[0]), "r"(bb[1]));
}

// ---------------------------------------------------------------- utilities
__global__ void k_zero() {
    int i = blockIdx.x * blockDim.x + threadIdx.x;
    if (i < NM) g_Z[i] = 0.f;
    if (i < NB * NS) g_wnum[i] = 0.f;
}

// g_Wc[kk][o] = conv_w[o][i][k],  kk = k*256 + i
__global__ void k_tw(const float* __restrict__ conv_w) {
    int kk = blockIdx.x;
    int o  = threadIdx.x;
    int i = kk & 255, k = kk >> 8;
    g_Wc[kk * NP + o] = conv_w[o * NKC + i * 3 + k];
}

// Reordered+transposed attn_w -> bf16 hi/lo.  n' = q*8+h.
__global__ void k_tb(const float* __restrict__ aw, const float* __restrict__ ab) {
    int np = blockIdx.x;          // n' in [0,4096)
    int k  = threadIdx.x;         // [0,256)
    int q = np >> 3, h = np & 7;
    float v = aw[(size_t)k * NHS + h * NS + q];
    __nv_bfloat16 hi = __float2bfloat16(v);
    float lo = v - __bfloat162float(hi);
    g_BtH[(size_t)np * NP + k] = hi;
    g_BtL[(size_t)np * NP + k] = __float2bfloat16(lo);
    if (k == 0) g_abr[np] = ab[h * NS + q];
}

// base[q] = sum_h softmax(attn_b)[h*S+q]  (contribution of a fully-masked row)
__global__ void k_base(const float* __restrict__ ab) {
    __shared__ float red[512];
    int t = threadIdx.x;
    float mx = -1e30f;
    for (int j = t; j < NHS; j += 512) mx = fmaxf(mx, ab[j]);
    red[t] = mx; __syncthreads();
    for (int s = 256; s; s >>= 1) { if (t < s) red[t] = fmaxf(red[t], red[t + s]); __syncthreads(); }
    mx = red[0]; __syncthreads();
    float sum = 0.f;
    for (int j = t; j < NHS; j += 512) sum += __expf(ab[j] - mx);
    red[t] = sum; __syncthreads();
    for (int s = 256; s; s >>= 1) { if (t < s) red[t] += red[t + s]; __syncthreads(); }
    float z0 = red[0];
    float acc = 0.f;
    for (int h = 0; h < NH; h++) acc += __expf(ab[h * NS + t] - mx);
    g_base[t] = acc / z0;
}

// ---------------------------------------------------------------- SGEMM cores
// 128x128x8 tile, 256 threads, 8x8 per-thread microtile, double-buffered smem.

#define SG_DECL                                                   \
    __shared__ float As[2][8][132];                               \
    __shared__ float Bs[2][8][128];                               \
    const int tid = threadIdx.x;                                  \
    const int tx = tid & 15, ty = tid >> 4;                       \
    const int aRow = tid >> 1, aCol = (tid & 1) * 4;              \
    const int bRow = tid >> 5, bCol = (tid & 31) * 4;             \
    float acc[8][8];                                              \
    _Pragma("unroll") for (int i = 0; i < 8; i++)                 \
    _Pragma("unroll") for (int j = 0; j < 8; j++) acc[i][j] = 0.f;

#define SG_STORE_A(buf, av)                                       \
    As[buf][aCol + 0][aRow] = av.x; As[buf][aCol + 1][aRow] = av.y; \
    As[buf][aCol + 2][aRow] = av.z; As[buf][aCol + 3][aRow] = av.w;

#define SG_COMPUTE(buf)                                           \
    _Pragma("unroll")                                             \
    for (int kk = 0; kk < 8; kk++) {                              \
        float afr[8], bfr[8];                                     \
        *(float4*)&afr[0] = *(const float4*)&As[buf][kk][ty * 8];     \
        *(float4*)&afr[4] = *(const float4*)&As[buf][kk][ty * 8 + 4]; \
        *(float4*)&bfr[0] = *(const float4*)&Bs[buf][kk][tx * 8];     \
        *(float4*)&bfr[4] = *(const float4*)&Bs[buf][kk][tx * 8 + 4]; \
        _Pragma("unroll") for (int i = 0; i < 8; i++)             \
        _Pragma("unroll") for (int j = 0; j < 8; j++)             \
            acc[i][j] += afr[i] * bfr[j];                         \
    }

// proj = x @ proj_w + proj_b      [16384,1024]x[1024,256]
__global__ void __launch_bounds__(256, 2) k_proj(const float* __restrict__ X,
                                                 const float* __restrict__ W,
                                                 const float* __restrict__ bias) {
    SG_DECL
    const int m0 = blockIdx.x * 128;
    const int n0 = blockIdx.y * 128;
    {
        float4 av = *(const float4*)&X[(size_t)(m0 + aRow) * NE + aCol];
        float4 bv = *(const float4*)&W[(size_t)bRow * NP + n0 + bCol];
        SG_STORE_A(0, av)
        *(float4*)&Bs[0][bRow][bCol] = bv;
    }
    __syncthreads();
    const int KT = NE / 8;
    for (int kt = 0; kt < KT; kt++) {
        const int buf = kt & 1;
        float4 an, bn;
        if (kt + 1 < KT) {
            int k0 = (kt + 1) * 8;
            an = *(const float4*)&X[(size_t)(m0 + aRow) * NE + k0 + aCol];
            bn = *(const float4*)&W[(size_t)(k0 + bRow) * NP + n0 + bCol];
        }
        SG_COMPUTE(buf)
        if (kt + 1 < KT) {
            SG_STORE_A(buf ^ 1, an)
            *(float4*)&Bs[buf ^ 1][bRow][bCol] = bn;
        }
        __syncthreads();
    }
#pragma unroll
    for (int i = 0; i < 8; i++) {
        int row = m0 + ty * 8 + i;
#pragma unroll
        for (int j = 0; j < 8; j++)
            g_proj[(size_t)row * NP + n0 + tx * 8 + j] = acc[i][j] + bias[n0 + tx * 8 + j];
    }
}

// rep_conv = mask*relu(conv)  -> fp32 + bf16 hi/lo
__global__ void __launch_bounds__(256, 2) k_conv(const int* __restrict__ seqlen,
                                                 const float* __restrict__ cbias) {
    const int b = blockIdx.z;
    const int l = seqlen[b];
    const int s0 = blockIdx.x * 128;
    if (s0 >= l - 1) return;                       // fully masked tile
    SG_DECL
    const int n0 = blockIdx.y * 128;
    {
        int srow = s0 + aRow;                      // tap 0
        float4 av = *(const float4*)&g_proj[(size_t)(b * NS + srow) * NP + aCol];
        float4 bv = *(const float4*)&g_Wc[(size_t)bRow * NP + n0 + bCol];
        SG_STORE_A(0, av)
        *(float4*)&Bs[0][bRow][bCol] = bv;
    }
    __syncthreads();
    const int KT = NKC / 8;
    for (int kt = 0; kt < KT; kt++) {
        const int buf = kt & 1;
        float4 an, bn;
        if (kt + 1 < KT) {
            int k0 = (kt + 1) * 8;
            int tap = k0 >> 8;
            int i0 = (k0 & 255) + aCol;
            int srow = s0 + aRow + tap;
            an = make_float4(0.f, 0.f, 0.f, 0.f);
            if (srow < NS)
                an = *(const float4*)&g_proj[(size_t)(b * NS + srow) * NP + i0];
            bn = *(const float4*)&g_Wc[(size_t)(k0 + bRow) * NP + n0 + bCol];
        }
        SG_COMPUTE(buf)
        if (kt + 1 < KT) {
            SG_STORE_A(buf ^ 1, an)
            *(float4*)&Bs[buf ^ 1][bRow][bCol] = bn;
        }
        __syncthreads();
    }
#pragma unroll
    for (int i = 0; i < 8; i++) {
        int s = s0 + ty * 8 + i;
        bool valid = (s >= 1) && (s < l - 1);
#pragma unroll
        for (int j = 0; j < 8; j++) {
            int col = n0 + tx * 8 + j;
            float v = fmaxf(acc[i][j] + cbias[col], 0.f);
            v = valid ? v : 0.f;
            size_t idx = (size_t)(b * NS + s) * NP + col;
            g_rc[idx] = v;
            __nv_bfloat16 hi = __float2bfloat16(v);
            float lo = v - __bfloat162float(hi);
            g_rcH[idx] = hi;
            g_rcL[idx] = __float2bfloat16(lo);
        }
    }
}

// ---------------------------------------------------------------- mma.sync logits
// Block: D[128 s-rows x 128 n'] = rc[128x256] @ Bt^T (bf16 hi/lo 3-product).
// 8 warps: wm in [0,4) x wn in [0,2); warp tile 32x64 = 2 (m16) x 8 (n8) mma tiles.
// Epilogue: fold 8 heads/q -> g_A; row sums -> g_Z (atomics).
#define LDA 72                       /* bf16 row stride, conflict-free padding */
#define SM_T   (128 * LDA * 2)       /* 18432 bytes per tile */
#define SM_AH  0
#define SM_AL  (SM_T)
#define SM_BH  (2 * SM_T)
#define SM_BL  (3 * SM_T)
#define SM_AB  (4 * SM_T)
#define SMEM_LTM (SM_AB + 512)

__global__ void __launch_bounds__(256, 1) k_ltm(const int* __restrict__ seqlen) {
    const int ntb = blockIdx.x;           // n' tile [ntb*128, +128)
    const int b   = blockIdx.z;
    const int l   = seqlen[b];
    const int s0  = blockIdx.y * 128;
    if (s0 >= l - 1) return;
    extern __shared__ char sm[];
    const uint32_t smb = smem_to_u32(sm);
    __nv_bfloat16* sAH = (__nv_bfloat16*)(sm + SM_AH);
    __nv_bfloat16* sAL = (__nv_bfloat16*)(sm + SM_AL);
    __nv_bfloat16* sBH = (__nv_bfloat16*)(sm + SM_BH);
    __nv_bfloat16* sBL = (__nv_bfloat16*)(sm + SM_BL);
    float* abS = (float*)(sm + SM_AB);

    const int tid = threadIdx.x;
    const int lane = tid & 31, wid = tid >> 5;
    const int wm = wid >> 1, wn = wid & 1;
    const int g = lane >> 2, t = lane & 3;

    if (tid < 128) abS[tid] = g_abr[ntb * 128 + tid];

    float c[2][8][4];
#pragma unroll
    for (int i = 0; i < 2; i++)
#pragma unroll
        for (int j = 0; j < 8; j++)
#pragma unroll
            for (int k = 0; k < 4; k++) c[i][j][k] = 0.f;

    // precomputed ldmatrix lane offsets (element units)
    const int aLOff = (lane & 15) * LDA + (lane >> 4) * 8;                  // + mtile row base*LDA + k0
    const int bLOff = ((lane & 7) + ((lane >> 4) * 8)) * LDA + ((lane >> 3) & 1) * 8;

    for (int kc = 0; kc < 4; kc++) {
        __syncthreads();           // protect smem overwrite (also orders abS for epilogue)
#pragma unroll
        for (int i = 0; i < 4; i++) {
            int idx = i * 256 + tid;               // 1024 uint4 per tile
            int row = idx >> 3, col = (idx & 7) * 8;
            size_t ga = (size_t)(b * NS + s0 + row) * NP + kc * 64 + col;
            size_t gb = (size_t)(ntb * 128 + row) * NP + kc * 64 + col;
            *(uint4*)(sAH + row * LDA + col) = *(const uint4*)(g_rcH + ga);
            *(uint4*)(sAL + row * LDA + col) = *(const uint4*)(g_rcL + ga);
            *(uint4*)(sBH + row * LDA + col) = *(const uint4*)(g_BtH + gb);
            *(uint4*)(sBL + row * LDA + col) = *(const uint4*)(g_BtL + gb);
        }
        __syncthreads();
#pragma unroll
        for (int kk = 0; kk < 4; kk++) {
            const int k0 = kk * 16;
            uint32_t ah[2][4], al[2][4], bh[8][2], bl[8][2];
#pragma unroll
            for (int mt = 0; mt < 2; mt++) {
                uint32_t addr = smb + SM_AH +
                    (uint32_t)(((wm * 32 + mt * 16) * LDA + k0 + aLOff) * 2);
                ldsm_x4(ah[mt], addr);
                ldsm_x4(al[mt], addr + SM_T);
            }
#pragma unroll
            for (int np2 = 0; np2 < 4; np2++) {
                uint32_t addr = smb + SM_BH +
                    (uint32_t)(((wn * 64 + np2 * 16) * LDA + k0 + bLOff) * 2);
                uint32_t r[4];
                ldsm_x4(r, addr);
                bh[np2 * 2][0] = r[0]; bh[np2 * 2][1] = r[1];
                bh[np2 * 2 + 1][0] = r[2]; bh[np2 * 2 + 1][1] = r[3];
                ldsm_x4(r, addr + SM_T);
                bl[np2 * 2][0] = r[0]; bl[np2 * 2][1] = r[1];
                bl[np2 * 2 + 1][0] = r[2]; bl[np2 * 2 + 1][1] = r[3];
            }
#pragma unroll
            for (int mt = 0; mt < 2; mt++)
#pragma unroll
                for (int nt = 0; nt < 8; nt++) {
                    mma_bf16(c[mt][nt], ah[mt], bh[nt]);   // hi*hi
                    mma_bf16(c[mt][nt], ah[mt], bl[nt]);   // hi*lo
                    mma_bf16(c[mt][nt], al[mt], bh[nt]);   // lo*hi
                }
        }
    }

    // Epilogue: exp + head-fold + row sums
    const int sr = b * NS + s0;
#pragma unroll
    for (int mt = 0; mt < 2; mt++) {
        const int r0 = wm * 32 + mt * 16 + g;
        const int r1 = r0 + 8;
        float z0 = 0.f, z1 = 0.f;
#pragma unroll
        for (int nt = 0; nt < 8; nt++) {
            const int lc = wn * 64 + nt * 8 + 2 * t;
            float e00 = __expf(c[mt][nt][0] + abS[lc]);
            float e01 = __expf(c[mt][nt][1] + abS[lc + 1]);
            float e10 = __expf(c[mt][nt][2] + abS[lc]);
            float e11 = __expf(c[mt][nt][3] + abS[lc + 1]);
            float s0v = e00 + e01, s1v = e10 + e11;
            s0v += __shfl_xor_sync(0xFFFFFFFFu, s0v, 1);
            s0v += __shfl_xor_sync(0xFFFFFFFFu, s0v, 2);
            s1v += __shfl_xor_sync(0xFFFFFFFFu, s1v, 1);
            s1v += __shfl_xor_sync(0xFFFFFFFFu, s1v, 2);
            z0 += s0v; z1 += s1v;
            if (t == 0) {
                const int q = ntb * 16 + wn * 8 + nt;
                g_A[(size_t)(sr + r0) * NS + q] = s0v;
                g_A[(size_t)(sr + r1) * NS + q] = s1v;
            }
        }
        if (t == 0) {
            atomicAdd(&g_Z[sr + r0], z0);
            atomicAdd(&g_Z[sr + r1], z1);
        }
    }
}

// wnum[b,q] = sum over processed rows s of g_A[b,s,q] / Z[b,s]
__global__ void __launch_bounds__(512) k_w(const int* __restrict__ seqlen) {
    const int b = blockIdx.x;
    const int q = threadIdx.x;
    const int l = seqlen[b];
    int pe = ((l - 1 + 127) >> 7) << 7;
    if (pe > NS) pe = NS;
    float acc = 0.f;
    size_t basei = (size_t)b * NS * NS + q;
#pragma unroll 4
    for (int s = 0; s < pe; s++)
        acc += g_A[basei + (size_t)s * NS] / g_Z[b * NS + s];
    g_wnum[b * NS + q] = acc;
}

// Finalize: w, rep_attn, classifier, softmax, argmax -> out
__global__ void __launch_bounds__(256) k_ra(const int* __restrict__ seqlen,
                                            const float* __restrict__ c1w,
                                            const float* __restrict__ c1b,
                                            const float* __restrict__ c2w,
                                            const float* __restrict__ c2b,
                                            float* __restrict__ out, int out_size) {
    __shared__ float w_sh[NS];
    __shared__ float ra[NP];
    __shared__ float h_sh[128];
    __shared__ float cls[2];
    const int b = blockIdx.x;
    const int t = threadIdx.x;
    const int l = seqlen[b];
    int pe = ((l - 1 + 127) / 128) * 128;
    if (pe > NS) pe = NS;
    float nmask = (float)(NS - pe);
    for (int q = t; q < NS; q += 256)
        w_sh[q] = (g_wnum[b * NS + q] + nmask * g_base[q]) * (1.0f / NH);
    __syncthreads();

    float acc = 0.f;
    for (int q = 1; q < l - 1; q++)
        acc += w_sh[q] * g_rc[(size_t)(b * NS + q) * NP + t];
    ra[t] = acc;
    __syncthreads();

    if (t < 128) {
        float hv = c1b[t];
        for (int p = 0; p < NP; p++) hv += ra[p] * c1w[p * 128 + t];
        h_sh[t] = hv > 0.f ? hv : 0.01f * hv;
    }
    __syncthreads();
    if (t < 2) {
        float cv = c2b[t];
        for (int j = 0; j < 128; j++) cv += h_sh[j] * c2w[j * 2 + t];
        cls[t] = cv;
    }
    __syncthreads();
    if (t == 0) {
        float m  = fmaxf(cls[0], cls[1]);
        float e0 = __expf(cls[0] - m), e1 = __expf(cls[1] - m);
        float inv = 1.f / (e0 + e1);
        float p0 = e0 * inv, p1 = e1 * inv;
        out[2 * b]     = p0;
        out[2 * b + 1] = p1;
        if (out_size >= 2 * NB + NB)
            out[2 * NB + b] = (p1 > p0) ? 1.0f : 0.0f;
    }
}

// ---------------------------------------------------------------- launch
extern "C" void kernel_launch(void* const* d_in, const int* in_sizes, int n_in,
                              void* d_out, int out_size) {
    const float* x      = (const float*)d_in[0];
    const int*   seqlen = (const int*)  d_in[1];
    const float* proj_w = (const float*)d_in[2];
    const float* proj_b = (const float*)d_in[3];
    const float* conv_w = (const float*)d_in[4];
    const float* conv_b = (const float*)d_in[5];
    const float* attn_w = (const float*)d_in[6];
    const float* attn_b = (const float*)d_in[7];
    const float* c1_w   = (const float*)d_in[8];
    const float* c1_b   = (const float*)d_in[9];
    const float* c2_w   = (const float*)d_in[10];
    const float* c2_b   = (const float*)d_in[11];
    float* out = (float*)d_out;

    cudaFuncSetAttribute(k_ltm, cudaFuncAttributeMaxDynamicSharedMemorySize, SMEM_LTM);

    k_zero  <<<32, 512>>>();
    k_tw    <<<NKC, NP>>>(conv_w);
    k_tb    <<<NHS, NP>>>(attn_w, attn_b);
    k_base  <<<1, 512>>>(attn_b);
    k_proj  <<<dim3(NM / 128, NP / 128), 256>>>(x, proj_w, proj_b);
    k_conv  <<<dim3(NS / 128, NP / 128, NB), 256>>>(seqlen, conv_b);
    k_ltm   <<<dim3(NHS / 128, NS / 128, NB), 256, SMEM_LTM>>>(seqlen);
    k_w     <<<NB, 512>>>(seqlen);
    k_ra    <<<NB, 256>>>(seqlen, c1_w, c1_b, c2_w, c2_b, out, out_size);
}

// round 6
// speedup vs baseline: 1.5792x; 1.5792x over previous
#include <cuda_runtime.h>
#include <cuda_bf16.h>
#include <cstdint>

// Dims
#define NB 32
#define NS 512
#define NE 1024
#define NP 256
#define NH 8
#define NHS 4096      /* NH*NS */
#define NM 16384      /* NB*NS */
#define NKC 768       /* NP*3 conv reduction */

// Scratch (allowed: __device__ globals)
__device__ __align__(16) float g_proj[(size_t)NM * NP];         // 16 MB
__device__ __align__(16) float g_rc[(size_t)NM * NP];           // 16 MB  rep_conv fp32
__device__ __align__(16) __nv_bfloat16 g_rcH[(size_t)NM * NP];  // 8 MB rep_conv bf16 hi
__device__ __align__(16) __nv_bfloat16 g_rcL[(size_t)NM * NP];  // 8 MB rep_conv bf16 lo
__device__ __align__(16) __nv_bfloat16 g_BtH[(size_t)NHS * NP]; // 2 MB attn_w^T reordered hi
__device__ __align__(16) __nv_bfloat16 g_BtL[(size_t)NHS * NP]; // 2 MB lo
__device__ __align__(16) float g_A[(size_t)NB * NS * NS];       // 33.5 MB head-folded exp
__device__ __align__(16) float g_abr[NHS];                      // reordered attn_b
__device__ __align__(16) float g_Z[NM];                         // row sums
__device__ __align__(16) float g_wnum[NB * NS];                 // softmax-weight numerator
__device__ __align__(16) float g_Wc[NKC * NP];                  // transposed conv_w
__device__ __align__(16) float g_base[NS];                      // masked-row analytic contribution

// ================================================================ helpers
__device__ __forceinline__ uint32_t smem_to_u32(const void* p) {
    uint32_t a;
    asm("{ .reg .u64 t; cvta.to.shared.u64 t, %1; cvt.u32.u64 %0, t; }" : "=r"(a) : "l"(p));
    return a;
}
__device__ __forceinline__ void ldsm_x4(uint32_t* r, uint32_t addr) {
    asm volatile("ldmatrix.sync.aligned.m8n8.x4.shared.b16 {%0,%1,%2,%3}, [%4];"
                 : "=r"(r[0]), "=r"(r[1]), "=r"(r[2]), "=r"(r[3]) : "r"(addr));
}
__device__ __forceinline__ void mma_bf16(float* c, const uint32_t* a, const uint32_t* bb) {
    asm volatile(
        "mma.sync.aligned.m16n8k16.row.col.f32.bf16.bf16.f32 "
        "{%0,%1,%2,%3}, {%4,%5,%6,%7}, {%8,%9}, {%0,%1,%2,%3};"
        : "+f"(c[0]), "+f"(c[1]), "+f"(c[2]), "+f"(c[3])
        : "r"(a[0]), "r"(a[1]), "r"(a[2]), "r"(a[3]), "r"(bb[0]), "r"(bb[1]));
}
__device__ __forceinline__ void cp16(uint32_t smem, const void* g) {
    asm volatile("cp.async.ca.shared.global [%0], [%1], 16;" :: "r"(smem), "l"(g));
}
#define CP_COMMIT() asm volatile("cp.async.commit_group;" ::: "memory")
#define CP_WAIT1()  asm volatile("cp.async.wait_group 1;" ::: "memory")
#define CP_WAIT0()  asm volatile("cp.async.wait_group 0;" ::: "memory")

// ---------------------------------------------------------------- utilities
__global__ void k_zero() {
    int i = blockIdx.x * blockDim.x + threadIdx.x;
    if (i < NM) g_Z[i] = 0.f;
    if (i < NB * NS) g_wnum[i] = 0.f;
}

// g_Wc[kk][o] = conv_w[o][i][k],  kk = k*256 + i
__global__ void k_tw(const float* __restrict__ conv_w) {
    int kk = blockIdx.x;
    int o  = threadIdx.x;
    int i = kk & 255, k = kk >> 8;
    g_Wc[kk * NP + o] = conv_w[o * NKC + i * 3 + k];
}

// Reordered+transposed attn_w -> bf16 hi/lo.  n' = q*8+h.
__global__ void k_tb(const float* __restrict__ aw, const float* __restrict__ ab) {
    int np = blockIdx.x;          // n' in [0,4096)
    int k  = threadIdx.x;         // [0,256)
    int q = np >> 3, h = np & 7;
    float v = aw[(size_t)k * NHS + h * NS + q];
    __nv_bfloat16 hi = __float2bfloat16(v);
    float lo = v - __bfloat162float(hi);
    g_BtH[(size_t)np * NP + k] = hi;
    g_BtL[(size_t)np * NP + k] = __float2bfloat16(lo);
    if (k == 0) g_abr[np] = ab[h * NS + q];
}

// base[q] = sum_h softmax(attn_b)[h*S+q]  (contribution of a fully-masked row)
__global__ void k_base(const float* __restrict__ ab) {
    __shared__ float red[512];
    int t = threadIdx.x;
    float mx = -1e30f;
    for (int j = t; j < NHS; j += 512) mx = fmaxf(mx, ab[j]);
    red[t] = mx; __syncthreads();
    for (int s = 256; s; s >>= 1) { if (t < s) red[t] = fmaxf(red[t], red[t + s]); __syncthreads(); }
    mx = red[0]; __syncthreads();
    float sum = 0.f;
    for (int j = t; j < NHS; j += 512) sum += __expf(ab[j] - mx);
    red[t] = sum; __syncthreads();
    for (int s = 256; s; s >>= 1) { if (t < s) red[t] += red[t + s]; __syncthreads(); }
    float z0 = red[0];
    float acc = 0.f;
    for (int h = 0; h < NH; h++) acc += __expf(ab[h * NS + t] - mx);
    g_base[t] = acc / z0;
}

// ---------------------------------------------------------------- SGEMM cores
// 128x128x8 tile, 256 threads, 8x8 per-thread microtile, double-buffered smem.

#define SG_DECL                                                   \
    __shared__ float As[2][8][132];                               \
    __shared__ float Bs[2][8][128];                               \
    const int tid = threadIdx.x;                                  \
    const int tx = tid & 15, ty = tid >> 4;                       \
    const int aRow = tid >> 1, aCol = (tid & 1) * 4;              \
    const int bRow = tid >> 5, bCol = (tid & 31) * 4;             \
    float acc[8][8];                                              \
    _Pragma("unroll") for (int i = 0; i < 8; i++)                 \
    _Pragma("unroll") for (int j = 0; j < 8; j++) acc[i][j] = 0.f;

#define SG_STORE_A(buf, av)                                       \
    As[buf][aCol + 0][aRow] = av.x; As[buf][aCol + 1][aRow] = av.y; \
    As[buf][aCol + 2][aRow] = av.z; As[buf][aCol + 3][aRow] = av.w;

#define SG_COMPUTE(buf)                                           \
    _Pragma("unroll")                                             \
    for (int kk = 0; kk < 8; kk++) {                              \
        float afr[8], bfr[8];                                     \
        *(float4*)&afr[0] = *(const float4*)&As[buf][kk][ty * 8];     \
        *(float4*)&afr[4] = *(const float4*)&As[buf][kk][ty * 8 + 4]; \
        *(float4*)&bfr[0] = *(const float4*)&Bs[buf][kk][tx * 8];     \
        *(float4*)&bfr[4] = *(const float4*)&Bs[buf][kk][tx * 8 + 4]; \
        _Pragma("unroll") for (int i = 0; i < 8; i++)             \
        _Pragma("unroll") for (int j = 0; j < 8; j++)             \
            acc[i][j] += afr[i] * bfr[j];                         \
    }

// proj = x @ proj_w + proj_b      [16384,1024]x[1024,256]
__global__ void __launch_bounds__(256, 2) k_proj(const float* __restrict__ X,
                                                 const float* __restrict__ W,
                                                 const float* __restrict__ bias) {
    SG_DECL
    const int m0 = blockIdx.x * 128;
    const int n0 = blockIdx.y * 128;
    {
        float4 av = *(const float4*)&X[(size_t)(m0 + aRow) * NE + aCol];
        float4 bv = *(const float4*)&W[(size_t)bRow * NP + n0 + bCol];
        SG_STORE_A(0, av)
        *(float4*)&Bs[0][bRow][bCol] = bv;
    }
    __syncthreads();
    const int KT = NE / 8;
    for (int kt = 0; kt < KT; kt++) {
        const int buf = kt & 1;
        float4 an, bn;
        if (kt + 1 < KT) {
            int k0 = (kt + 1) * 8;
            an = *(const float4*)&X[(size_t)(m0 + aRow) * NE + k0 + aCol];
            bn = *(const float4*)&W[(size_t)(k0 + bRow) * NP + n0 + bCol];
        }
        SG_COMPUTE(buf)
        if (kt + 1 < KT) {
            SG_STORE_A(buf ^ 1, an)
            *(float4*)&Bs[buf ^ 1][bRow][bCol] = bn;
        }
        __syncthreads();
    }
#pragma unroll
    for (int i = 0; i < 8; i++) {
        int row = m0 + ty * 8 + i;
#pragma unroll
        for (int j = 0; j < 8; j++)
            g_proj[(size_t)row * NP + n0 + tx * 8 + j] = acc[i][j] + bias[n0 + tx * 8 + j];
    }
}

// rep_conv = mask*relu(conv)  -> fp32 + bf16 hi/lo
__global__ void __launch_bounds__(256, 2) k_conv(const int* __restrict__ seqlen,
                                                 const float* __restrict__ cbias) {
    const int b = blockIdx.z;
    const int l = seqlen[b];
    const int s0 = blockIdx.x * 128;
    if (s0 >= l - 1) return;                       // fully masked tile
    SG_DECL
    const int n0 = blockIdx.y * 128;
    {
        int srow = s0 + aRow;                      // tap 0
        float4 av = *(const float4*)&g_proj[(size_t)(b * NS + srow) * NP + aCol];
        float4 bv = *(const float4*)&g_Wc[(size_t)bRow * NP + n0 + bCol];
        SG_STORE_A(0, av)
        *(float4*)&Bs[0][bRow][bCol] = bv;
    }
    __syncthreads();
    const int KT = NKC / 8;
    for (int kt = 0; kt < KT; kt++) {
        const int buf = kt & 1;
        float4 an, bn;
        if (kt + 1 < KT) {
            int k0 = (kt + 1) * 8;
            int tap = k0 >> 8;
            int i0 = (k0 & 255) + aCol;
            int srow = s0 + aRow + tap;
            an = make_float4(0.f, 0.f, 0.f, 0.f);
            if (srow < NS)
                an = *(const float4*)&g_proj[(size_t)(b * NS + srow) * NP + i0];
            bn = *(const float4*)&g_Wc[(size_t)(k0 + bRow) * NP + n0 + bCol];
        }
        SG_COMPUTE(buf)
        if (kt + 1 < KT) {
            SG_STORE_A(buf ^ 1, an)
            *(float4*)&Bs[buf ^ 1][bRow][bCol] = bn;
        }
        __syncthreads();
    }
#pragma unroll
    for (int i = 0; i < 8; i++) {
        int s = s0 + ty * 8 + i;
        bool valid = (s >= 1) && (s < l - 1);
#pragma unroll
        for (int j = 0; j < 8; j++) {
            int col = n0 + tx * 8 + j;
            float v = fmaxf(acc[i][j] + cbias[col], 0.f);
            v = valid ? v : 0.f;
            size_t idx = (size_t)(b * NS + s) * NP + col;
            g_rc[idx] = v;
            __nv_bfloat16 hi = __float2bfloat16(v);
            float lo = v - __bfloat162float(hi);
            g_rcH[idx] = hi;
            g_rcL[idx] = __float2bfloat16(lo);
        }
    }
}

// ---------------------------------------------------------------- mma.sync logits (pipelined)
// Block: D[128 s-rows x 128 n'] = rc[128x256] @ Bt^T (bf16 hi/lo 3-product).
// 8 warps (4M x 2N), warp tile 32x64. K chunked 8x32, cp.async double-buffered.
#define LDA2 40                       /* bf16 row stride per chunk tile (32 + 8 pad) */
#define T_BYTES (128 * LDA2 * 2)      /* 10240 per tile */
#define ST_BYTES (4 * T_BYTES)        /* AH AL BH BL per stage = 40960 */
#define SMEM_LTM (2 * ST_BYTES + 512)

#define PREFETCH(kc_, st_) do {                                              \
    uint32_t sb = smb + (uint32_t)((st_) * ST_BYTES);                        \
    _Pragma("unroll") for (int i = 0; i < 2; i++) {                          \
        int idx = i * 256 + tid;                                             \
        int row = idx >> 2, col = (idx & 3) * 8;                             \
        uint32_t so = (uint32_t)((row * LDA2 + col) * 2);                    \
        size_t ga = (size_t)(b * NS + s0 + row) * NP + (kc_) * 32 + col;     \
        size_t gb = (size_t)(ntb * 128 + row) * NP + (kc_) * 32 + col;       \
        cp16(sb + so,               g_rcH + ga);                             \
        cp16(sb + T_BYTES + so,     g_rcL + ga);                             \
        cp16(sb + 2 * T_BYTES + so, g_BtH + gb);                             \
        cp16(sb + 3 * T_BYTES + so, g_BtL + gb);                             \
    }                                                                        \
} while (0)

__global__ void __launch_bounds__(256, 2) k_ltm(const int* __restrict__ seqlen) {
    const int ntb = blockIdx.x;           // n' tile [ntb*128, +128)
    const int b   = blockIdx.z;
    const int l   = seqlen[b];
    const int s0  = blockIdx.y * 128;
    if (s0 >= l - 1) return;
    extern __shared__ char sm[];
    const uint32_t smb = smem_to_u32(sm);
    float* abS = (float*)(sm + 2 * ST_BYTES);

    const int tid = threadIdx.x;
    const int lane = tid & 31, wid = tid >> 5;
    const int wm = wid >> 1, wn = wid & 1;
    const int g = lane >> 2, t = lane & 3;

    if (tid < 128) abS[tid] = g_abr[ntb * 128 + tid];

    float c[2][8][4];
#pragma unroll
    for (int i = 0; i < 2; i++)
#pragma unroll
        for (int j = 0; j < 8; j++)
#pragma unroll
            for (int k = 0; k < 4; k++) c[i][j][k] = 0.f;

    // ldmatrix lane offsets (element units)
    const int aLOff = (lane & 15) * LDA2 + (lane >> 4) * 8;
    const int bLOff = ((lane & 7) + ((lane >> 4) * 8)) * LDA2 + ((lane >> 3) & 1) * 8;

    PREFETCH(0, 0); CP_COMMIT();

    for (int kc = 0; kc < 8; kc++) {
        const int st = kc & 1;
        if (kc + 1 < 8) { PREFETCH(kc + 1, st ^ 1); CP_COMMIT(); CP_WAIT1(); }
        else            { CP_WAIT0(); }
        __syncthreads();                 // stage st ready for all warps

        const uint32_t base = smb + (uint32_t)(st * ST_BYTES);
#pragma unroll
        for (int kk = 0; kk < 2; kk++) {
            const int k0 = kk * 16;
            uint32_t ah[2][4], al[2][4], bh[8][2], bl[8][2];
#pragma unroll
            for (int mt = 0; mt < 2; mt++) {
                uint32_t addr = base +
                    (uint32_t)(((wm * 32 + mt * 16) * LDA2 + k0 + aLOff) * 2);
                ldsm_x4(ah[mt], addr);
                ldsm_x4(al[mt], addr + T_BYTES);
            }
#pragma unroll
            for (int np2 = 0; np2 < 4; np2++) {
                uint32_t addr = base + 2 * T_BYTES +
                    (uint32_t)(((wn * 64 + np2 * 16) * LDA2 + k0 + bLOff) * 2);
                uint32_t r[4];
                ldsm_x4(r, addr);
                bh[np2 * 2][0] = r[0]; bh[np2 * 2][1] = r[1];
                bh[np2 * 2 + 1][0] = r[2]; bh[np2 * 2 + 1][1] = r[3];
                ldsm_x4(r, addr + T_BYTES);
                bl[np2 * 2][0] = r[0]; bl[np2 * 2][1] = r[1];
                bl[np2 * 2 + 1][0] = r[2]; bl[np2 * 2 + 1][1] = r[3];
            }
#pragma unroll
            for (int mt = 0; mt < 2; mt++)
#pragma unroll
                for (int nt = 0; nt < 8; nt++) {
                    mma_bf16(c[mt][nt], ah[mt], bh[nt]);   // hi*hi
                    mma_bf16(c[mt][nt], ah[mt], bl[nt]);   // hi*lo
                    mma_bf16(c[mt][nt], al[mt], bh[nt]);   // lo*hi
                }
        }
        __syncthreads();                 // all warps done with stage st before overwrite
    }

    // Epilogue: exp + head-fold + row sums
    const int sr = b * NS + s0;
#pragma unroll
    for (int mt = 0; mt < 2; mt++) {
        const int r0 = wm * 32 + mt * 16 + g;
        const int r1 = r0 + 8;
        float z0 = 0.f, z1 = 0.f;
#pragma unroll
        for (int nt = 0; nt < 8; nt++) {
            const int lc = wn * 64 + nt * 8 + 2 * t;
            float e00 = __expf(c[mt][nt][0] + abS[lc]);
            float e01 = __expf(c[mt][nt][1] + abS[lc + 1]);
            float e10 = __expf(c[mt][nt][2] + abS[lc]);
            float e11 = __expf(c[mt][nt][3] + abS[lc + 1]);
            float s0v = e00 + e01, s1v = e10 + e11;
            s0v += __shfl_xor_sync(0xFFFFFFFFu, s0v, 1);
            s0v += __shfl_xor_sync(0xFFFFFFFFu, s0v, 2);
            s1v += __shfl_xor_sync(0xFFFFFFFFu, s1v, 1);
            s1v += __shfl_xor_sync(0xFFFFFFFFu, s1v, 2);
            z0 += s0v; z1 += s1v;
            if (t == 0) {
                const int q = ntb * 16 + wn * 8 + nt;
                g_A[(size_t)(sr + r0) * NS + q] = s0v;
                g_A[(size_t)(sr + r1) * NS + q] = s1v;
            }
        }
        if (t == 0) {
            atomicAdd(&g_Z[sr + r0], z0);
            atomicAdd(&g_Z[sr + r1], z1);
        }
    }
}

// wnum[b,q] = sum over processed rows s of g_A[b,s,q] / Z[b,s]
__global__ void __launch_bounds__(512) k_w(const int* __restrict__ seqlen) {
    const int b = blockIdx.x;
    const int q = threadIdx.x;
    const int l = seqlen[b];
    int pe = ((l - 1 + 127) >> 7) << 7;
    if (pe > NS) pe = NS;
    float acc = 0.f;
    size_t basei = (size_t)b * NS * NS + q;
#pragma unroll 4
    for (int s = 0; s < pe; s++)
        acc += g_A[basei + (size_t)s * NS] / g_Z[b * NS + s];
    g_wnum[b * NS + q] = acc;
}

// Finalize: w, rep_attn, classifier, softmax, argmax -> out
__global__ void __launch_bounds__(256) k_ra(const int* __restrict__ seqlen,
                                            const float* __restrict__ c1w,
                                            const float* __restrict__ c1b,
                                            const float* __restrict__ c2w,
                                            const float* __restrict__ c2b,
                                            float* __restrict__ out, int out_size) {
    __shared__ float w_sh[NS];
    __shared__ float ra[NP];
    __shared__ float h_sh[128];
    __shared__ float cls[2];
    const int b = blockIdx.x;
    const int t = threadIdx.x;
    const int l = seqlen[b];
    int pe = ((l - 1 + 127) / 128) * 128;
    if (pe > NS) pe = NS;
    float nmask = (float)(NS - pe);
    for (int q = t; q < NS; q += 256)
        w_sh[q] = (g_wnum[b * NS + q] + nmask * g_base[q]) * (1.0f / NH);
    __syncthreads();

    float acc = 0.f;
    for (int q = 1; q < l - 1; q++)
        acc += w_sh[q] * g_rc[(size_t)(b * NS + q) * NP + t];
    ra[t] = acc;
    __syncthreads();

    if (t < 128) {
        float hv = c1b[t];
        for (int p = 0; p < NP; p++) hv += ra[p] * c1w[p * 128 + t];
        h_sh[t] = hv > 0.f ? hv : 0.01f * hv;
    }
    __syncthreads();
    if (t < 2) {
        float cv = c2b[t];
        for (int j = 0; j < 128; j++) cv += h_sh[j] * c2w[j * 2 + t];
        cls[t] = cv;
    }
    __syncthreads();
    if (t == 0) {
        float m  = fmaxf(cls[0], cls[1]);
        float e0 = __expf(cls[0] - m), e1 = __expf(cls[1] - m);
        float inv = 1.f / (e0 + e1);
        float p0 = e0 * inv, p1 = e1 * inv;
        out[2 * b]     = p0;
        out[2 * b + 1] = p1;
        if (out_size >= 2 * NB + NB)
            out[2 * NB + b] = (p1 > p0) ? 1.0f : 0.0f;
    }
}

// ---------------------------------------------------------------- launch
extern "C" void kernel_launch(void* const* d_in, const int* in_sizes, int n_in,
                              void* d_out, int out_size) {
    const float* x      = (const float*)d_in[0];
    const int*   seqlen = (const int*)  d_in[1];
    const float* proj_w = (const float*)d_in[2];
    const float* proj_b = (const float*)d_in[3];
    const float* conv_w = (const float*)d_in[4];
    const float* conv_b = (const float*)d_in[5];
    const float* attn_w = (const float*)d_in[6];
    const float* attn_b = (const float*)d_in[7];
    const float* c1_w   = (const float*)d_in[8];
    const float* c1_b   = (const float*)d_in[9];
    const float* c2_w   = (const float*)d_in[10];
    const float* c2_b   = (const float*)d_in[11];
    float* out = (float*)d_out;

    cudaFuncSetAttribute(k_ltm, cudaFuncAttributeMaxDynamicSharedMemorySize, SMEM_LTM);

    k_zero  <<<32, 512>>>();
    k_tw    <<<NKC, NP>>>(conv_w);
    k_tb    <<<NHS, NP>>>(attn_w, attn_b);
    k_base  <<<1, 512>>>(attn_b);
    k_proj  <<<dim3(NM / 128, NP / 128), 256>>>(x, proj_w, proj_b);
    k_conv  <<<dim3(NS / 128, NP / 128, NB), 256>>>(seqlen, conv_b);
    k_ltm   <<<dim3(NHS / 128, NS / 128, NB), 256, SMEM_LTM>>>(seqlen);
    k_w     <<<NB, 512>>>(seqlen);
    k_ra    <<<NB, 256>>>(seqlen, c1_w, c1_b, c2_w, c2_b, out, out_size);
}

// round 7
// speedup vs baseline: 2.1353x; 1.3521x over previous
#include <cuda_runtime.h>
#include <cuda_bf16.h>
#include <cstdint>

// Dims
#define NB 32
#define NS 512
#define NE 1024
#define NP 256
#define NH 8
#define NHS 4096      /* NH*NS */
#define NM 16384      /* NB*NS */
#define NKC 768       /* NP*3 conv reduction */

// Scratch (allowed: __device__ globals)
__device__ __align__(16) __nv_bfloat16 g_xH[(size_t)NM * NE];   // 33.5 MB x hi
__device__ __align__(16) __nv_bfloat16 g_xL[(size_t)NM * NE];   // 33.5 MB x lo
__device__ __align__(16) __nv_bfloat16 g_pwH[(size_t)NP * NE];  // proj_w^T hi [n][k]
__device__ __align__(16) __nv_bfloat16 g_pwL[(size_t)NP * NE];
__device__ __align__(16) __nv_bfloat16 g_pjH[(size_t)NM * NP];  // proj hi
__device__ __align__(16) __nv_bfloat16 g_pjL[(size_t)NM * NP];  // proj lo
__device__ __align__(16) __nv_bfloat16 g_WtH[(size_t)NP * NKC]; // conv_w^T hi [o][kk]
__device__ __align__(16) __nv_bfloat16 g_WtL[(size_t)NP * NKC];
__device__ __align__(16) float g_rc[(size_t)NM * NP];           // 16 MB rep_conv fp32
__device__ __align__(16) __nv_bfloat16 g_rcH[(size_t)NM * NP];  // 8 MB rep_conv hi
__device__ __align__(16) __nv_bfloat16 g_rcL[(size_t)NM * NP];  // 8 MB rep_conv lo
__device__ __align__(16) __nv_bfloat16 g_BtH[(size_t)NHS * NP]; // attn_w^T reordered hi
__device__ __align__(16) __nv_bfloat16 g_BtL[(size_t)NHS * NP];
__device__ __align__(16) float g_A[(size_t)NB * NS * NS];       // 33.5 MB head-folded exp
__device__ __align__(16) float g_abr[NHS];                      // reordered attn_b
__device__ __align__(16) float g_Z[NM];                         // row sums
__device__ __align__(16) float g_wnum[NB * NS];                 // softmax-weight numerator
__device__ __align__(16) float g_base[NS];                      // masked-row analytic contribution

// ================================================================ helpers
__device__ __forceinline__ uint32_t smem_to_u32(const void* p) {
    uint32_t a;
    asm("{ .reg .u64 t; cvta.to.shared.u64 t, %1; cvt.u32.u64 %0, t; }" : "=r"(a) : "l"(p));
    return a;
}
__device__ __forceinline__ void ldsm_x4(uint32_t* r, uint32_t addr) {
    asm volatile("ldmatrix.sync.aligned.m8n8.x4.shared.b16 {%0,%1,%2,%3}, [%4];"
                 : "=r"(r[0]), "=r"(r[1]), "=r"(r[2]), "=r"(r[3]) : "r"(addr));
}
__device__ __forceinline__ void mma_bf16(float* c, const uint32_t* a, const uint32_t* bb) {
    asm volatile(
        "mma.sync.aligned.m16n8k16.row.col.f32.bf16.bf16.f32 "
        "{%0,%1,%2,%3}, {%4,%5,%6,%7}, {%8,%9}, {%0,%1,%2,%3};"
        : "+f"(c[0]), "+f"(c[1]), "+f"(c[2]), "+f"(c[3])
        : "r"(a[0]), "r"(a[1]), "r"(a[2]), "r"(a[3]), "r"(bb[0]), "r"(bb[1]));
}
__device__ __forceinline__ void cp16(uint32_t smem, const void* g) {
    asm volatile("cp.async.ca.shared.global [%0], [%1], 16;" :: "r"(smem), "l"(g));
}
__device__ __forceinline__ void cp16z(uint32_t smem, const void* g, uint32_t sz) {
    asm volatile("cp.async.ca.shared.global [%0], [%1], 16, %2;" :: "r"(smem), "l"(g), "r"(sz));
}
#define CP_COMMIT() asm volatile("cp.async.commit_group;" ::: "memory")
#define CP_WAIT1()  asm volatile("cp.async.wait_group 1;" ::: "memory")
#define CP_WAIT0()  asm volatile("cp.async.wait_group 0;" ::: "memory")

__device__ __forceinline__ void split_store(__nv_bfloat16* pH, __nv_bfloat16* pL,
                                            float a, float b) {
    __nv_bfloat162 h, lo;
    h.x = __float2bfloat16(a); h.y = __float2bfloat16(b);
    lo.x = __float2bfloat16(a - __bfloat162float(h.x));
    lo.y = __float2bfloat16(b - __bfloat162float(h.y));
    *(__nv_bfloat162*)pH = h;
    *(__nv_bfloat162*)pL = lo;
}

// ---------------------------------------------------------------- small prep kernels
__global__ void k_zero() {
    int i = blockIdx.x * blockDim.x + threadIdx.x;
    if (i < NM) g_Z[i] = 0.f;
    if (i < NB * NS) g_wnum[i] = 0.f;
}

// split x -> bf16 hi/lo
__global__ void k_sx(const float* __restrict__ x) {
    size_t idx = ((size_t)blockIdx.x * 256 + threadIdx.x) * 4;
    float4 v = *(const float4*)(x + idx);
    split_store(g_xH + idx,     g_xL + idx,     v.x, v.y);
    split_store(g_xH + idx + 2, g_xL + idx + 2, v.z, v.w);
}

// proj_w [E,P] -> pwT [P,E] hi/lo
__global__ void k_tpw(const float* __restrict__ pw) {
    int o = blockIdx.x;
    for (int k = threadIdx.x; k < NE; k += 256) {
        float v = pw[(size_t)k * NP + o];
        __nv_bfloat16 hi = __float2bfloat16(v);
        g_pwH[(size_t)o * NE + k] = hi;
        g_pwL[(size_t)o * NE + k] = __float2bfloat16(v - __bfloat162float(hi));
    }
}

// conv_w [O,I,K3] -> WcT [o][kk], kk = k*256 + i, hi/lo
__global__ void k_twc(const float* __restrict__ cw) {
    int o = blockIdx.x;
    for (int kk = threadIdx.x; kk < NKC; kk += 256) {
        int i = kk & 255, k = kk >> 8;
        float v = cw[(size_t)o * NKC + i * 3 + k];
        __nv_bfloat16 hi = __float2bfloat16(v);
        g_WtH[(size_t)o * NKC + kk] = hi;
        g_WtL[(size_t)o * NKC + kk] = __float2bfloat16(v - __bfloat162float(hi));
    }
}

// Reordered+transposed attn_w -> bf16 hi/lo.  n' = q*8+h.
__global__ void k_tb(const float* __restrict__ aw, const float* __restrict__ ab) {
    int np = blockIdx.x;
    int k  = threadIdx.x;
    int q = np >> 3, h = np & 7;
    float v = aw[(size_t)k * NHS + h * NS + q];
    __nv_bfloat16 hi = __float2bfloat16(v);
    g_BtH[(size_t)np * NP + k] = hi;
    g_BtL[(size_t)np * NP + k] = __float2bfloat16(v - __bfloat162float(hi));
    if (k == 0) g_abr[np] = ab[h * NS + q];
}

// base[q] = sum_h softmax(attn_b)[h*S+q]
__global__ void k_base(const float* __restrict__ ab) {
    __shared__ float red[512];
    int t = threadIdx.x;
    float mx = -1e30f;
    for (int j = t; j < NHS; j += 512) mx = fmaxf(mx, ab[j]);
    red[t] = mx; __syncthreads();
    for (int s = 256; s; s >>= 1) { if (t < s) red[t] = fmaxf(red[t], red[t + s]); __syncthreads(); }
    mx = red[0]; __syncthreads();
    float sum = 0.f;
    for (int j = t; j < NHS; j += 512) sum += __expf(ab[j] - mx);
    red[t] = sum; __syncthreads();
    for (int s = 256; s; s >>= 1) { if (t < s) red[t] += red[t + s]; __syncthreads(); }
    float z0 = red[0];
    float acc = 0.f;
    for (int h = 0; h < NH; h++) acc += __expf(ab[h * NS + t] - mx);
    g_base[t] = acc / z0;
}

// ---------------------------------------------------------------- pipelined mma core
// 128x128 block tile, 8 warps (4M x 2N), K chunks of 32, cp.async 2-stage.
#define LDA2 40
#define T_BYTES (128 * LDA2 * 2)      /* 10240 per tile */
#define ST_BYTES (4 * T_BYTES)        /* AH AL BH BL per stage */
#define SMEM_MMA (2 * ST_BYTES + 512)

#define MMA_DECL                                                          \
    extern __shared__ char sm[];                                          \
    const uint32_t smb = smem_to_u32(sm);                                 \
    float* exS = (float*)(sm + 2 * ST_BYTES);                             \
    const int tid = threadIdx.x;                                          \
    const int lane = tid & 31, wid = tid >> 5;                            \
    const int wm = wid >> 1, wn = wid & 1;                                \
    const int g = lane >> 2, t = lane & 3;                                \
    float c[2][8][4];                                                     \
    _Pragma("unroll") for (int i = 0; i < 2; i++)                         \
    _Pragma("unroll") for (int j = 0; j < 8; j++)                         \
    _Pragma("unroll") for (int k = 0; k < 4; k++) c[i][j][k] = 0.f;       \
    const int aLOff = (lane & 15) * LDA2 + (lane >> 4) * 8;               \
    const int bLOff = ((lane & 7) + ((lane >> 4) * 8)) * LDA2 + ((lane >> 3) & 1) * 8;

#define MMA_COMPUTE(st_)                                                      \
    {                                                                         \
        const uint32_t base = smb + (uint32_t)((st_) * ST_BYTES);             \
        _Pragma("unroll")                                                     \
        for (int kk = 0; kk < 2; kk++) {                                      \
            const int k0 = kk * 16;                                           \
            uint32_t ah[2][4], al[2][4], bh[8][2], bl[8][2];                  \
            _Pragma("unroll")                                                 \
            for (int mt = 0; mt < 2; mt++) {                                  \
                uint32_t addr = base +                                        \
                    (uint32_t)(((wm * 32 + mt * 16) * LDA2 + k0 + aLOff) * 2);\
                ldsm_x4(ah[mt], addr);                                        \
                ldsm_x4(al[mt], addr + T_BYTES);                              \
            }                                                                 \
            _Pragma("unroll")                                                 \
            for (int np2 = 0; np2 < 4; np2++) {                               \
                uint32_t addr = base + 2 * T_BYTES +                          \
                    (uint32_t)(((wn * 64 + np2 * 16) * LDA2 + k0 + bLOff) * 2);\
                uint32_t r[4];                                                \
                ldsm_x4(r, addr);                                             \
                bh[np2 * 2][0] = r[0]; bh[np2 * 2][1] = r[1];                 \
                bh[np2 * 2 + 1][0] = r[2]; bh[np2 * 2 + 1][1] = r[3];         \
                ldsm_x4(r, addr + T_BYTES);                                   \
                bl[np2 * 2][0] = r[0]; bl[np2 * 2][1] = r[1];                 \
                bl[np2 * 2 + 1][0] = r[2]; bl[np2 * 2 + 1][1] = r[3];         \
            }                                                                 \
            _Pragma("unroll")                                                 \
            for (int mt = 0; mt < 2; mt++)                                    \
                _Pragma("unroll")                                             \
                for (int nt = 0; nt < 8; nt++) {                              \
                    mma_bf16(c[mt][nt], ah[mt], bh[nt]);                      \
                    mma_bf16(c[mt][nt], ah[mt], bl[nt]);                      \
                    mma_bf16(c[mt][nt], al[mt], bh[nt]);                      \
                }                                                             \
        }                                                                     \
    }

// ---------------------------------------------------------------- proj (mma)
// proj[m, n] = x[m,:1024] @ pwT[n,:1024] + pb[n]  -> bf16 hi/lo only
__global__ void __launch_bounds__(256, 2) k_pm(const float* __restrict__ pb) {
    const int n0 = blockIdx.x * 128;
    const int m0 = blockIdx.y * 128;
    MMA_DECL
    if (tid < 128) exS[tid] = pb[n0 + tid];

#define PF_P(kc_, st_) do {                                                  \
    uint32_t sb = smb + (uint32_t)((st_) * ST_BYTES);                        \
    _Pragma("unroll") for (int i = 0; i < 2; i++) {                          \
        int idx = i * 256 + tid;                                             \
        int row = idx >> 2, col = (idx & 3) * 8;                             \
        uint32_t so = (uint32_t)((row * LDA2 + col) * 2);                    \
        size_t ga = (size_t)(m0 + row) * NE + (kc_) * 32 + col;              \
        size_t gb = (size_t)(n0 + row) * NE + (kc_) * 32 + col;              \
        cp16(sb + so,               g_xH + ga);                              \
        cp16(sb + T_BYTES + so,     g_xL + ga);                              \
        cp16(sb + 2 * T_BYTES + so, g_pwH + gb);                             \
        cp16(sb + 3 * T_BYTES + so, g_pwL + gb);                             \
    }                                                                        \
} while (0)

    PF_P(0, 0); CP_COMMIT();
    for (int kc = 0; kc < 32; kc++) {
        const int st = kc & 1;
        if (kc + 1 < 32) { PF_P(kc + 1, st ^ 1); CP_COMMIT(); CP_WAIT1(); }
        else             { CP_WAIT0(); }
        __syncthreads();
        MMA_COMPUTE(st)
        __syncthreads();
    }
#pragma unroll
    for (int mt = 0; mt < 2; mt++) {
        const int r0 = m0 + wm * 32 + mt * 16 + g;
#pragma unroll
        for (int nt = 0; nt < 8; nt++) {
            const int lc = wn * 64 + nt * 8 + 2 * t;
            const int col = n0 + lc;
            float b0 = exS[lc], b1 = exS[lc + 1];
            split_store(g_pjH + (size_t)r0 * NP + col, g_pjL + (size_t)r0 * NP + col,
                        c[mt][nt][0] + b0, c[mt][nt][1] + b1);
            split_store(g_pjH + (size_t)(r0 + 8) * NP + col, g_pjL + (size_t)(r0 + 8) * NP + col,
                        c[mt][nt][2] + b0, c[mt][nt][3] + b1);
        }
    }
}

// ---------------------------------------------------------------- conv (mma)
// rc[b,s,o] = mask*relu( sum_kk proj[b, s+tap, i] * WcT[o,kk] + cb[o] )
__global__ void __launch_bounds__(256, 2) k_cm(const int* __restrict__ seqlen,
                                               const float* __restrict__ cb) {
    const int n0 = blockIdx.x * 128;
    const int s0 = blockIdx.y * 128;
    const int b  = blockIdx.z;
    const int l  = seqlen[b];
    if (s0 >= l - 1) return;
    MMA_DECL
    if (tid < 128) exS[tid] = cb[n0 + tid];

#define PF_C(kc_, st_) do {                                                  \
    uint32_t sb = smb + (uint32_t)((st_) * ST_BYTES);                        \
    const int tap = (kc_) >> 3;                                              \
    const int i0 = ((kc_) & 7) * 32;                                         \
    _Pragma("unroll") for (int i = 0; i < 2; i++) {                          \
        int idx = i * 256 + tid;                                             \
        int row = idx >> 2, col = (idx & 3) * 8;                             \
        uint32_t so = (uint32_t)((row * LDA2 + col) * 2);                    \
        int srow = s0 + row + tap;                                           \
        uint32_t sz = (srow < NS) ? 16u : 0u;                                \
        int srcl = (srow < NS) ? srow : (NS - 1);                            \
        size_t ga = (size_t)(b * NS + srcl) * NP + i0 + col;                 \
        size_t gb = (size_t)(n0 + row) * NKC + (kc_) * 32 + col;             \
        cp16z(sb + so,           g_pjH + ga, sz);                            \
        cp16z(sb + T_BYTES + so, g_pjL + ga, sz);                            \
        cp16(sb + 2 * T_BYTES + so, g_WtH + gb);                             \
        cp16(sb + 3 * T_BYTES + so, g_WtL + gb);                             \
    }                                                                        \
} while (0)

    PF_C(0, 0); CP_COMMIT();
    for (int kc = 0; kc < 24; kc++) {
        const int st = kc & 1;
        if (kc + 1 < 24) { PF_C(kc + 1, st ^ 1); CP_COMMIT(); CP_WAIT1(); }
        else             { CP_WAIT0(); }
        __syncthreads();
        MMA_COMPUTE(st)
        __syncthreads();
    }
#pragma unroll
    for (int mt = 0; mt < 2; mt++) {
#pragma unroll
        for (int rr = 0; rr < 2; rr++) {
            const int s = s0 + wm * 32 + mt * 16 + rr * 8 + g;
            const bool valid = (s >= 1) && (s < l - 1);
            const size_t rowo = (size_t)(b * NS + s) * NP;
#pragma unroll
            for (int nt = 0; nt < 8; nt++) {
                const int lc = wn * 64 + nt * 8 + 2 * t;
                const int col = n0 + lc;
                float v0 = fmaxf(c[mt][nt][rr * 2 + 0] + exS[lc], 0.f);
                float v1 = fmaxf(c[mt][nt][rr * 2 + 1] + exS[lc + 1], 0.f);
                v0 = valid ? v0 : 0.f;
                v1 = valid ? v1 : 0.f;
                *(float2*)&g_rc[rowo + col] = make_float2(v0, v1);
                split_store(g_rcH + rowo + col, g_rcL + rowo + col, v0, v1);
            }
        }
    }
}

// ---------------------------------------------------------------- mma logits (pipelined)
__global__ void __launch_bounds__(256, 2) k_ltm(const int* __restrict__ seqlen) {
    const int ntb = blockIdx.x;
    const int b   = blockIdx.z;
    const int l   = seqlen[b];
    const int s0  = blockIdx.y * 128;
    if (s0 >= l - 1) return;
    MMA_DECL
    if (tid < 128) exS[tid] = g_abr[ntb * 128 + tid];

#define PF_L(kc_, st_) do {                                                  \
    uint32_t sb = smb + (uint32_t)((st_) * ST_BYTES);                        \
    _Pragma("unroll") for (int i = 0; i < 2; i++) {                          \
        int idx = i * 256 + tid;                                             \
        int row = idx >> 2, col = (idx & 3) * 8;                             \
        uint32_t so = (uint32_t)((row * LDA2 + col) * 2);                    \
        size_t ga = (size_t)(b * NS + s0 + row) * NP + (kc_) * 32 + col;     \
        size_t gb = (size_t)(ntb * 128 + row) * NP + (kc_) * 32 + col;       \
        cp16(sb + so,               g_rcH + ga);                             \
        cp16(sb + T_BYTES + so,     g_rcL + ga);                             \
        cp16(sb + 2 * T_BYTES + so, g_BtH + gb);                             \
        cp16(sb + 3 * T_BYTES + so, g_BtL + gb);                             \
    }                                                                        \
} while (0)

    PF_L(0, 0); CP_COMMIT();
    for (int kc = 0; kc < 8; kc++) {
        const int st = kc & 1;
        if (kc + 1 < 8) { PF_L(kc + 1, st ^ 1); CP_COMMIT(); CP_WAIT1(); }
        else            { CP_WAIT0(); }
        __syncthreads();
        MMA_COMPUTE(st)
        __syncthreads();
    }

    // Epilogue: exp + head-fold + row sums
    const int sr = b * NS + s0;
#pragma unroll
    for (int mt = 0; mt < 2; mt++) {
        const int r0 = wm * 32 + mt * 16 + g;
        const int r1 = r0 + 8;
        float z0 = 0.f, z1 = 0.f;
#pragma unroll
        for (int nt = 0; nt < 8; nt++) {
            const int lc = wn * 64 + nt * 8 + 2 * t;
            float e00 = __expf(c[mt][nt][0] + exS[lc]);
            float e01 = __expf(c[mt][nt][1] + exS[lc + 1]);
            float e10 = __expf(c[mt][nt][2] + exS[lc]);
            float e11 = __expf(c[mt][nt][3] + exS[lc + 1]);
            float s0v = e00 + e01, s1v = e10 + e11;
            s0v += __shfl_xor_sync(0xFFFFFFFFu, s0v, 1);
            s0v += __shfl_xor_sync(0xFFFFFFFFu, s0v, 2);
            s1v += __shfl_xor_sync(0xFFFFFFFFu, s1v, 1);
            s1v += __shfl_xor_sync(0xFFFFFFFFu, s1v, 2);
            z0 += s0v; z1 += s1v;
            if (t == 0) {
                const int q = ntb * 16 + wn * 8 + nt;
                g_A[(size_t)(sr + r0) * NS + q] = s0v;
                g_A[(size_t)(sr + r1) * NS + q] = s1v;
            }
        }
        if (t == 0) {
            atomicAdd(&g_Z[sr + r0], z0);
            atomicAdd(&g_Z[sr + r1], z1);
        }
    }
}

// wnum[b,q] = sum over processed rows s of g_A[b,s,q] / Z[b,s]
__global__ void __launch_bounds__(512) k_w(const int* __restrict__ seqlen) {
    const int b = blockIdx.x;
    const int q = threadIdx.x;
    const int l = seqlen[b];
    int pe = ((l - 1 + 127) >> 7) << 7;
    if (pe > NS) pe = NS;
    float acc = 0.f;
    size_t basei = (size_t)b * NS * NS + q;
#pragma unroll 4
    for (int s = 0; s < pe; s++)
        acc += g_A[basei + (size_t)s * NS] / g_Z[b * NS + s];
    g_wnum[b * NS + q] = acc;
}

// Finalize: w, rep_attn, classifier, softmax, argmax -> out
__global__ void __launch_bounds__(256) k_ra(const int* __restrict__ seqlen,
                                            const float* __restrict__ c1w,
                                            const float* __restrict__ c1b,
                                            const float* __restrict__ c2w,
                                            const float* __restrict__ c2b,
                                            float* __restrict__ out, int out_size) {
    __shared__ float w_sh[NS];
    __shared__ float ra[NP];
    __shared__ float h_sh[128];
    __shared__ float cls[2];
    const int b = blockIdx.x;
    const int t = threadIdx.x;
    const int l = seqlen[b];
    int pe = ((l - 1 + 127) / 128) * 128;
    if (pe > NS) pe = NS;
    float nmask = (float)(NS - pe);
    for (int q = t; q < NS; q += 256)
        w_sh[q] = (g_wnum[b * NS + q] + nmask * g_base[q]) * (1.0f / NH);
    __syncthreads();

    float acc = 0.f;
    for (int q = 1; q < l - 1; q++)
        acc += w_sh[q] * g_rc[(size_t)(b * NS + q) * NP + t];
    ra[t] = acc;
    __syncthreads();

    if (t < 128) {
        float hv = c1b[t];
        for (int p = 0; p < NP; p++) hv += ra[p] * c1w[p * 128 + t];
        h_sh[t] = hv > 0.f ? hv : 0.01f * hv;
    }
    __syncthreads();
    if (t < 2) {
        float cv = c2b[t];
        for (int j = 0; j < 128; j++) cv += h_sh[j] * c2w[j * 2 + t];
        cls[t] = cv;
    }
    __syncthreads();
    if (t == 0) {
        float m  = fmaxf(cls[0], cls[1]);
        float e0 = __expf(cls[0] - m), e1 = __expf(cls[1] - m);
        float inv = 1.f / (e0 + e1);
        float p0 = e0 * inv, p1 = e1 * inv;
        out[2 * b]     = p0;
        out[2 * b + 1] = p1;
        if (out_size >= 2 * NB + NB)
            out[2 * NB + b] = (p1 > p0) ? 1.0f : 0.0f;
    }
}

// ---------------------------------------------------------------- launch
extern "C" void kernel_launch(void* const* d_in, const int* in_sizes, int n_in,
                              void* d_out, int out_size) {
    const float* x      = (const float*)d_in[0];
    const int*   seqlen = (const int*)  d_in[1];
    const float* proj_w = (const float*)d_in[2];
    const float* proj_b = (const float*)d_in[3];
    const float* conv_w = (const float*)d_in[4];
    const float* conv_b = (const float*)d_in[5];
    const float* attn_w = (const float*)d_in[6];
    const float* attn_b = (const float*)d_in[7];
    const float* c1_w   = (const float*)d_in[8];
    const float* c1_b   = (const float*)d_in[9];
    const float* c2_w   = (const float*)d_in[10];
    const float* c2_b   = (const float*)d_in[11];
    float* out = (float*)d_out;

    cudaFuncSetAttribute(k_pm,  cudaFuncAttributeMaxDynamicSharedMemorySize, SMEM_MMA);
    cudaFuncSetAttribute(k_cm,  cudaFuncAttributeMaxDynamicSharedMemorySize, SMEM_MMA);
    cudaFuncSetAttribute(k_ltm, cudaFuncAttributeMaxDynamicSharedMemorySize, SMEM_MMA);

    k_zero <<<32, 512>>>();
    k_sx   <<<NM * NE / 1024, 256>>>(x);
    k_tpw  <<<NP, 256>>>(proj_w);
    k_twc  <<<NP, 256>>>(conv_w);
    k_tb   <<<NHS, NP>>>(attn_w, attn_b);
    k_base <<<1, 512>>>(attn_b);
    k_pm   <<<dim3(NP / 128, NM / 128), 256, SMEM_MMA>>>(proj_b);
    k_cm   <<<dim3(NP / 128, NS / 128, NB), 256, SMEM_MMA>>>(seqlen, conv_b);
    k_ltm  <<<dim3(NHS / 128, NS / 128, NB), 256, SMEM_MMA>>>(seqlen);
    k_w    <<<NB, 512>>>(seqlen);
    k_ra   <<<NB, 256>>>(seqlen, c1_w, c1_b, c2_w, c2_b, out, out_size);
}

// round 9
// speedup vs baseline: 2.4251x; 1.1358x over previous
#include <cuda_runtime.h>
#include <cuda_bf16.h>
#include <cstdint>

// Dims
#define NB 32
#define NS 512
#define NE 1024
#define NP 256
#define NH 8
#define NHS 4096      /* NH*NS */
#define NM 16384      /* NB*NS */
#define NKC 768       /* NP*3 conv reduction */

// Scratch (allowed: __device__ globals)
__device__ __align__(16) __nv_bfloat16 g_xH[(size_t)NM * NE];   // x hi
__device__ __align__(16) __nv_bfloat16 g_xL[(size_t)NM * NE];   // x lo
__device__ __align__(16) __nv_bfloat16 g_pwH[(size_t)NP * NE];  // proj_w^T hi [n][k]
__device__ __align__(16) __nv_bfloat16 g_pwL[(size_t)NP * NE];
__device__ __align__(16) __nv_bfloat16 g_pjH[(size_t)NM * NP];  // proj hi
__device__ __align__(16) __nv_bfloat16 g_pjL[(size_t)NM * NP];  // proj lo
__device__ __align__(16) __nv_bfloat16 g_WtH[(size_t)NP * NKC]; // conv_w^T hi [o][kk]
__device__ __align__(16) __nv_bfloat16 g_WtL[(size_t)NP * NKC];
__device__ __align__(16) float g_rc[(size_t)NM * NP];           // rep_conv fp32
__device__ __align__(16) __nv_bfloat16 g_rcH[(size_t)NM * NP];  // rep_conv hi
__device__ __align__(16) __nv_bfloat16 g_rcL[(size_t)NM * NP];  // rep_conv lo
__device__ __align__(16) __nv_bfloat16 g_BtH[(size_t)NHS * NP]; // attn_w^T reordered hi
__device__ __align__(16) __nv_bfloat16 g_BtL[(size_t)NHS * NP];
__device__ __align__(16) float g_A[(size_t)NB * NS * NS];       // head-folded exp
__device__ __align__(16) float g_abr[NHS];                      // reordered attn_b
__device__ __align__(16) float g_wnum[NB * NS];                 // softmax-weight numerator
__device__ __align__(16) float g_base[NS];                      // masked-row analytic contribution

// ================================================================ helpers
__device__ __forceinline__ uint32_t smem_to_u32(const void* p) {
    uint32_t a;
    asm("{ .reg .u64 t; cvta.to.shared.u64 t, %1; cvt.u32.u64 %0, t; }" : "=r"(a) : "l"(p));
    return a;
}
__device__ __forceinline__ void ldsm_x4(uint32_t* r, uint32_t addr) {
    asm volatile("ldmatrix.sync.aligned.m8n8.x4.shared.b16 {%0,%1,%2,%3}, [%4];"
                 : "=r"(r[0]), "=r"(r[1]), "=r"(r[2]), "=r"(r[3]) : "r"(addr));
}
__device__ __forceinline__ void mma_bf16(float* c, const uint32_t* a, const uint32_t* bb) {
    asm volatile(
        "mma.sync.aligned.m16n8k16.row.col.f32.bf16.bf16.f32 "
        "{%0,%1,%2,%3}, {%4,%5,%6,%7}, {%8,%9}, {%0,%1,%2,%3};"
        : "+f"(c[0]), "+f"(c[1]), "+f"(c[2]), "+f"(c[3])
        : "r"(a[0]), "r"(a[1]), "r"(a[2]), "r"(a[3]), "r"(bb[0]), "r"(bb[1]));
}
__device__ __forceinline__ void cp16(uint32_t smem, const void* g) {
    asm volatile("cp.async.ca.shared.global [%0], [%1], 16;" :: "r"(smem), "l"(g));
}
__device__ __forceinline__ void cp16z(uint32_t smem, const void* g, uint32_t sz) {
    asm volatile("cp.async.ca.shared.global [%0], [%1], 16, %2;" :: "r"(smem), "l"(g), "r"(sz));
}
#define CP_COMMIT() asm volatile("cp.async.commit_group;" ::: "memory")
#define CP_WAIT1()  asm volatile("cp.async.wait_group 1;" ::: "memory")
#define CP_WAIT0()  asm volatile("cp.async.wait_group 0;" ::: "memory")

__device__ __forceinline__ void split_store(__nv_bfloat16* pH, __nv_bfloat16* pL,
                                            float a, float b) {
    __nv_bfloat162 h, lo;
    h.x = __float2bfloat16(a); h.y = __float2bfloat16(b);
    lo.x = __float2bfloat16(a - __bfloat162float(h.x));
    lo.y = __float2bfloat16(b - __bfloat162float(h.y));
    *(__nv_bfloat162*)pH = h;
    *(__nv_bfloat162*)pL = lo;
}

// ---------------------------------------------------------------- prep kernels
// split x -> bf16 hi/lo
__global__ void k_sx(const float* __restrict__ x) {
    size_t idx = ((size_t)blockIdx.x * 256 + threadIdx.x) * 4;
    float4 v = *(const float4*)(x + idx);
    split_store(g_xH + idx,     g_xL + idx,     v.x, v.y);
    split_store(g_xH + idx + 2, g_xL + idx + 2, v.z, v.w);
}

// Combined prep: proj_w^T, conv_w^T, attn_w^T(reordered), base.
__global__ void k_prep(const float* __restrict__ pw, const float* __restrict__ cw,
                       const float* __restrict__ aw, const float* __restrict__ ab) {
    const int bid = blockIdx.x;
    if (bid < NP) {                        // proj_w [E,P] -> [P,E] hi/lo
        int o = bid;
        for (int k = threadIdx.x; k < NE; k += 256) {
            float v = pw[(size_t)k * NP + o];
            __nv_bfloat16 hi = __float2bfloat16(v);
            g_pwH[(size_t)o * NE + k] = hi;
            g_pwL[(size_t)o * NE + k] = __float2bfloat16(v - __bfloat162float(hi));
        }
    } else if (bid < 2 * NP) {             // conv_w [O,I,K3] -> [o][kk], kk=k*256+i
        int o = bid - NP;
        for (int kk = threadIdx.x; kk < NKC; kk += 256) {
            int i = kk & 255, k = kk >> 8;
            float v = cw[(size_t)o * NKC + i * 3 + k];
            __nv_bfloat16 hi = __float2bfloat16(v);
            g_WtH[(size_t)o * NKC + kk] = hi;
            g_WtL[(size_t)o * NKC + kk] = __float2bfloat16(v - __bfloat162float(hi));
        }
    } else if (bid < 2 * NP + NHS) {       // attn_w reorder+transpose, n' = q*8+h
        int np = bid - 2 * NP;
        int k  = threadIdx.x;
        int q = np >> 3, h = np & 7;
        float v = aw[(size_t)k * NHS + h * NS + q];
        __nv_bfloat16 hi = __float2bfloat16(v);
        g_BtH[(size_t)np * NP + k] = hi;
        g_BtL[(size_t)np * NP + k] = __float2bfloat16(v - __bfloat162float(hi));
        if (k == 0) g_abr[np] = ab[h * NS + q];
    } else {                               // base[q] = sum_h softmax(attn_b)[h*S+q]
        __shared__ float red[256];
        int t = threadIdx.x;
        float mx = -1e30f;
        for (int j = t; j < NHS; j += 256) mx = fmaxf(mx, ab[j]);
        red[t] = mx; __syncthreads();
        for (int s = 128; s; s >>= 1) { if (t < s) red[t] = fmaxf(red[t], red[t + s]); __syncthreads(); }
        mx = red[0]; __syncthreads();
        float sum = 0.f;
        for (int j = t; j < NHS; j += 256) sum += __expf(ab[j] - mx);
        red[t] = sum; __syncthreads();
        for (int s = 128; s; s >>= 1) { if (t < s) red[t] += red[t + s]; __syncthreads(); }
        float z0 = red[0];
        for (int q = t; q < NS; q += 256) {
            float acc = 0.f;
            for (int h = 0; h < NH; h++) acc += __expf(ab[h * NS + q] - mx);
            g_base[q] = acc / z0;
        }
    }
}

// ---------------------------------------------------------------- pipelined mma core (k_pm/k_cm)
// 128x128 block tile, 8 warps (4M x 2N), K chunks of 32, cp.async 2-stage.
#define LDA2 40
#define T_BYTES (128 * LDA2 * 2)      /* 10240 per tile */
#define ST_BYTES (4 * T_BYTES)        /* AH AL BH BL per stage */
#define SMEM_MMA (2 * ST_BYTES + 512)

#define MMA_DECL                                                          \
    extern __shared__ char sm[];                                          \
    const uint32_t smb = smem_to_u32(sm);                                 \
    float* exS = (float*)(sm + 2 * ST_BYTES);                             \
    const int tid = threadIdx.x;                                          \
    const int lane = tid & 31, wid = tid >> 5;                            \
    const int wm = wid >> 1, wn = wid & 1;                                \
    const int g = lane >> 2, t = lane & 3;                                \
    float c[2][8][4];                                                     \
    _Pragma("unroll") for (int i = 0; i < 2; i++)                         \
    _Pragma("unroll") for (int j = 0; j < 8; j++)                         \
    _Pragma("unroll") for (int k = 0; k < 4; k++) c[i][j][k] = 0.f;       \
    const int aLOff = (lane & 15) * LDA2 + (lane >> 4) * 8;               \
    const int bLOff = ((lane & 7) + ((lane >> 4) * 8)) * LDA2 + ((lane >> 3) & 1) * 8;

#define MMA_COMPUTE(st_)                                                      \
    {                                                                         \
        const uint32_t base = smb + (uint32_t)((st_) * ST_BYTES);             \
        _Pragma("unroll")                                                     \
        for (int kk = 0; kk < 2; kk++) {                                      \
            const int k0 = kk * 16;                                           \
            uint32_t ah[2][4], al[2][4], bh[8][2], bl[8][2];                  \
            _Pragma("unroll")                                                 \
            for (int mt = 0; mt < 2; mt++) {                                  \
                uint32_t addr = base +                                        \
                    (uint32_t)(((wm * 32 + mt * 16) * LDA2 + k0 + aLOff) * 2);\
                ldsm_x4(ah[mt], addr);                                        \
                ldsm_x4(al[mt], addr + T_BYTES);                              \
            }                                                                 \
            _Pragma("unroll")                                                 \
            for (int np2 = 0; np2 < 4; np2++) {                               \
                uint32_t addr = base + 2 * T_BYTES +                          \
                    (uint32_t)(((wn * 64 + np2 * 16) * LDA2 + k0 + bLOff) * 2);\
                uint32_t r[4];                                                \
                ldsm_x4(r, addr);                                             \
                bh[np2 * 2][0] = r[0]; bh[np2 * 2][1] = r[1];                 \
                bh[np2 * 2 + 1][0] = r[2]; bh[np2 * 2 + 1][1] = r[3];         \
                ldsm_x4(r, addr + T_BYTES);                                   \
                bl[np2 * 2][0] = r[0]; bl[np2 * 2][1] = r[1];                 \
                bl[np2 * 2 + 1][0] = r[2]; bl[np2 * 2 + 1][1] = r[3];         \
            }                                                                 \
            _Pragma("unroll")                                                 \
            for (int mt = 0; mt < 2; mt++)                                    \
                _Pragma("unroll")                                             \
                for (int nt = 0; nt < 8; nt++) {                              \
                    mma_bf16(c[mt][nt], ah[mt], bh[nt]);                      \
                    mma_bf16(c[mt][nt], ah[mt], bl[nt]);                      \
                    mma_bf16(c[mt][nt], al[mt], bh[nt]);                      \
                }                                                             \
        }                                                                     \
    }

// ---------------------------------------------------------------- proj (mma)
__global__ void __launch_bounds__(256, 2) k_pm(const float* __restrict__ pb) {
    const int n0 = blockIdx.x * 128;
    const int m0 = blockIdx.y * 128;
    MMA_DECL
    if (tid < 128) exS[tid] = pb[n0 + tid];

#define PF_P(kc_, st_) do {                                                  \
    uint32_t sb = smb + (uint32_t)((st_) * ST_BYTES);                        \
    _Pragma("unroll") for (int i = 0; i < 2; i++) {                          \
        int idx = i * 256 + tid;                                             \
        int row = idx >> 2, col = (idx & 3) * 8;                             \
        uint32_t so = (uint32_t)((row * LDA2 + col) * 2);                    \
        size_t ga = (size_t)(m0 + row) * NE + (kc_) * 32 + col;              \
        size_t gb = (size_t)(n0 + row) * NE + (kc_) * 32 + col;              \
        cp16(sb + so,               g_xH + ga);                              \
        cp16(sb + T_BYTES + so,     g_xL + ga);                              \
        cp16(sb + 2 * T_BYTES + so, g_pwH + gb);                             \
        cp16(sb + 3 * T_BYTES + so, g_pwL + gb);                             \
    }                                                                        \
} while (0)

    PF_P(0, 0); CP_COMMIT();
    for (int kc = 0; kc < 32; kc++) {
        const int st = kc & 1;
        if (kc + 1 < 32) { PF_P(kc + 1, st ^ 1); CP_COMMIT(); CP_WAIT1(); }
        else             { CP_WAIT0(); }
        __syncthreads();
        MMA_COMPUTE(st)
        __syncthreads();
    }
#pragma unroll
    for (int mt = 0; mt < 2; mt++) {
        const int r0 = m0 + wm * 32 + mt * 16 + g;
#pragma unroll
        for (int nt = 0; nt < 8; nt++) {
            const int lc = wn * 64 + nt * 8 + 2 * t;
            const int col = n0 + lc;
            float b0 = exS[lc], b1 = exS[lc + 1];
            split_store(g_pjH + (size_t)r0 * NP + col, g_pjL + (size_t)r0 * NP + col,
                        c[mt][nt][0] + b0, c[mt][nt][1] + b1);
            split_store(g_pjH + (size_t)(r0 + 8) * NP + col, g_pjL + (size_t)(r0 + 8) * NP + col,
                        c[mt][nt][2] + b0, c[mt][nt][3] + b1);
        }
    }
}

// ---------------------------------------------------------------- conv (mma)
__global__ void __launch_bounds__(256, 2) k_cm(const int* __restrict__ seqlen,
                                               const float* __restrict__ cb) {
    const int n0 = blockIdx.x * 128;
    const int s0 = blockIdx.y * 128;
    const int b  = blockIdx.z;
    const int l  = seqlen[b];
    if (s0 >= l - 1) return;
    MMA_DECL
    if (tid < 128) exS[tid] = cb[n0 + tid];

#define PF_C(kc_, st_) do {                                                  \
    uint32_t sb = smb + (uint32_t)((st_) * ST_BYTES);                        \
    const int tap = (kc_) >> 3;                                              \
    const int i0 = ((kc_) & 7) * 32;                                         \
    _Pragma("unroll") for (int i = 0; i < 2; i++) {                          \
        int idx = i * 256 + tid;                                             \
        int row = idx >> 2, col = (idx & 3) * 8;                             \
        uint32_t so = (uint32_t)((row * LDA2 + col) * 2);                    \
        int srow = s0 + row + tap;                                           \
        uint32_t sz = (srow < NS) ? 16u : 0u;                                \
        int srcl = (srow < NS) ? srow : (NS - 1);                            \
        size_t ga = (size_t)(b * NS + srcl) * NP + i0 + col;                 \
        size_t gb = (size_t)(n0 + row) * NKC + (kc_) * 32 + col;             \
        cp16z(sb + so,           g_pjH + ga, sz);                            \
        cp16z(sb + T_BYTES + so, g_pjL + ga, sz);                            \
        cp16(sb + 2 * T_BYTES + so, g_WtH + gb);                             \
        cp16(sb + 3 * T_BYTES + so, g_WtL + gb);                             \
    }                                                                        \
} while (0)

    PF_C(0, 0); CP_COMMIT();
    for (int kc = 0; kc < 24; kc++) {
        const int st = kc & 1;
        if (kc + 1 < 24) { PF_C(kc + 1, st ^ 1); CP_COMMIT(); CP_WAIT1(); }
        else             { CP_WAIT0(); }
        __syncthreads();
        MMA_COMPUTE(st)
        __syncthreads();
    }
#pragma unroll
    for (int mt = 0; mt < 2; mt++) {
#pragma unroll
        for (int rr = 0; rr < 2; rr++) {
            const int s = s0 + wm * 32 + mt * 16 + rr * 8 + g;
            const bool valid = (s >= 1) && (s < l - 1);
            const size_t rowo = (size_t)(b * NS + s) * NP;
#pragma unroll
            for (int nt = 0; nt < 8; nt++) {
                const int lc = wn * 64 + nt * 8 + 2 * t;
                const int col = n0 + lc;
                float v0 = fmaxf(c[mt][nt][rr * 2 + 0] + exS[lc], 0.f);
                float v1 = fmaxf(c[mt][nt][rr * 2 + 1] + exS[lc + 1], 0.f);
                v0 = valid ? v0 : 0.f;
                v1 = valid ? v1 : 0.f;
                *(float2*)&g_rc[rowo + col] = make_float2(v0, v1);
                split_store(g_rcH + rowo + col, g_rcL + rowo + col, v0, v1);
            }
        }
    }
}

// ---------------------------------------------------------------- logits (resident-B mma)
// Grid (ntb, b), 512 threads = 16 warps (4M x 4N, warp tile 32x32).
// B (128 n' x 256 K, hi/lo) resident in smem; A streamed per s-tile, 2-stage.
#define LDB 264
#define B_TILE_B (128 * LDB * 2)          /* 67584 */
#define A_ST_B   (128 * LDA2 * 2)         /* 10240 per tile */
#define A_STAGE  (2 * A_ST_B)             /* hi+lo = 20480 */
#define OFF_A2   (2 * B_TILE_B)           /* 135168 */
#define OFF_EX2  (OFF_A2 + 2 * A_STAGE)   /* 176128 */
#define SMEM_LT2 (OFF_EX2 + 512)

__global__ void __launch_bounds__(512, 1) k_ltm(const int* __restrict__ seqlen) {
    const int ntb = blockIdx.x;
    const int b   = blockIdx.y;
    const int l   = seqlen[b];
    extern __shared__ char sm[];
    const uint32_t smb = smem_to_u32(sm);
    float* exS = (float*)(sm + OFF_EX2);
    const int tid = threadIdx.x;
    const int lane = tid & 31, wid = tid >> 5;
    const int wm = wid >> 2, wn = wid & 3;
    const int g = lane >> 2, t = lane & 3;

    if (tid < 128) exS[tid] = g_abr[ntb * 128 + tid];

    // Resident B load (hi+lo), 8192 cp16 over 512 threads.
#pragma unroll
    for (int i = 0; i < 8; i++) {
        int idx = i * 512 + tid;               // 4096 per tile
        int row = idx >> 5, col = (idx & 31) * 8;
        uint32_t so = (uint32_t)((row * LDB + col) * 2);
        size_t gb = (size_t)(ntb * 128 + row) * NP + col;
        cp16(smb + so,            g_BtH + gb);
        cp16(smb + B_TILE_B + so, g_BtL + gb);
    }
    CP_COMMIT();
    CP_WAIT0();               // B fully resident before mainloop (defensive)
    __syncthreads();

    const int aLOff = (lane & 15) * LDA2 + (lane >> 4) * 8;
    const int bLOff = ((lane & 7) + ((lane >> 4) * 8)) * LDB + ((lane >> 3) & 1) * 8;

#define PF_A2(kc_, st_) do {                                                 \
    uint32_t sb = smb + OFF_A2 + (uint32_t)((st_) * A_STAGE);                \
    int row = tid >> 2, col = (tid & 3) * 8;                                 \
    uint32_t so = (uint32_t)((row * LDA2 + col) * 2);                        \
    size_t ga = (size_t)(b * NS + s0 + row) * NP + (kc_) * 32 + col;         \
    cp16(sb + so,          g_rcH + ga);                                      \
    cp16(sb + A_ST_B + so, g_rcL + ga);                                      \
} while (0)

    for (int s0 = 0; s0 < l - 1; s0 += 128) {
        float c[2][4][4];
#pragma unroll
        for (int i = 0; i < 2; i++)
#pragma unroll
            for (int j = 0; j < 4; j++)
#pragma unroll
                for (int k = 0; k < 4; k++) c[i][j][k] = 0.f;

        PF_A2(0, 0); CP_COMMIT();
        for (int kc = 0; kc < 8; kc++) {
            const int st = kc & 1;
            if (kc + 1 < 8) { PF_A2(kc + 1, st ^ 1); CP_COMMIT(); CP_WAIT1(); }
            else            { CP_WAIT0(); }
            __syncthreads();
            const uint32_t abase = smb + OFF_A2 + (uint32_t)(st * A_STAGE);
#pragma unroll
            for (int kk = 0; kk < 2; kk++) {
                const int k0 = kk * 16;
                const int kg = kc * 32 + k0;
                uint32_t ah[2][4], al[2][4], bh[4][2], bl[4][2];
#pragma unroll
                for (int mt = 0; mt < 2; mt++) {
                    uint32_t addr = abase +
                        (uint32_t)(((wm * 32 + mt * 16) * LDA2 + k0 + aLOff) * 2);
                    ldsm_x4(ah[mt], addr);
                    ldsm_x4(al[mt], addr + A_ST_B);
                }
#pragma unroll
                for (int np2 = 0; np2 < 2; np2++) {
                    uint32_t addr = smb +
                        (uint32_t)(((wn * 32 + np2 * 16) * LDB + kg + bLOff) * 2);
                    uint32_t r[4];
                    ldsm_x4(r, addr);
                    bh[np2 * 2][0] = r[0]; bh[np2 * 2][1] = r[1];
                    bh[np2 * 2 + 1][0] = r[2]; bh[np2 * 2 + 1][1] = r[3];
                    ldsm_x4(r, addr + B_TILE_B);
                    bl[np2 * 2][0] = r[0]; bl[np2 * 2][1] = r[1];
                    bl[np2 * 2 + 1][0] = r[2]; bl[np2 * 2 + 1][1] = r[3];
                }
#pragma unroll
                for (int mt = 0; mt < 2; mt++)
#pragma unroll
                    for (int nt = 0; nt < 4; nt++) {
                        mma_bf16(c[mt][nt], ah[mt], bh[nt]);
                        mma_bf16(c[mt][nt], ah[mt], bl[nt]);
                        mma_bf16(c[mt][nt], al[mt], bh[nt]);
                    }
            }
            __syncthreads();
        }

        // Epilogue: exp + head-fold (8 n' = 1 q per nt tile) -> g_A
        const int sr = b * NS + s0;
#pragma unroll
        for (int mt = 0; mt < 2; mt++) {
            const int r0 = wm * 32 + mt * 16 + g;
            const int r1 = r0 + 8;
#pragma unroll
            for (int nt = 0; nt < 4; nt++) {
                const int lc = wn * 32 + nt * 8 + 2 * t;
                float e00 = __expf(c[mt][nt][0] + exS[lc]);
                float e01 = __expf(c[mt][nt][1] + exS[lc + 1]);
                float e10 = __expf(c[mt][nt][2] + exS[lc]);
                float e11 = __expf(c[mt][nt][3] + exS[lc + 1]);
                float s0v = e00 + e01, s1v = e10 + e11;
                s0v += __shfl_xor_sync(0xFFFFFFFFu, s0v, 1);
                s0v += __shfl_xor_sync(0xFFFFFFFFu, s0v, 2);
                s1v += __shfl_xor_sync(0xFFFFFFFFu, s1v, 1);
                s1v += __shfl_xor_sync(0xFFFFFFFFu, s1v, 2);
                if (t == 0) {
                    const int q = ntb * 16 + wn * 4 + nt;
                    g_A[(size_t)(sr + r0) * NS + q] = s0v;
                    g_A[(size_t)(sr + r1) * NS + q] = s1v;
                }
            }
        }
    }
}

// Z from row-sums of A, then wnum[b,q] = sum_s A[b,s,q]/Z[s]
__global__ void __launch_bounds__(512) k_w(const int* __restrict__ seqlen) {
    __shared__ float Zs[NS];
    const int b = blockIdx.x;
    const int tid = threadIdx.x;
    const int lane = tid & 31, w = tid >> 5;   // 16 warps
    const int l = seqlen[b];
    int pe = ((l - 1 + 127) >> 7) << 7;
    if (pe > NS) pe = NS;
    for (int s = w; s < pe; s += 16) {
        const float* row = g_A + (size_t)(b * NS + s) * NS;
        float acc = 0.f;
        for (int q = lane; q < NS; q += 32) acc += row[q];
#pragma unroll
        for (int o = 16; o; o >>= 1) acc += __shfl_xor_sync(0xFFFFFFFFu, acc, o);
        if (lane == 0) Zs[s] = 1.f / acc;
    }
    __syncthreads();
    for (int q = tid; q < NS; q += 512) {
        float acc = 0.f;
        size_t basei = (size_t)b * NS * NS + q;
#pragma unroll 4
        for (int s = 0; s < pe; s++)
            acc += g_A[basei + (size_t)s * NS] * Zs[s];
        g_wnum[b * NS + q] = acc;
    }
}

// Finalize: w, rep_attn, classifier, softmax, argmax -> out
__global__ void __launch_bounds__(256) k_ra(const int* __restrict__ seqlen,
                                            const float* __restrict__ c1w,
                                            const float* __restrict__ c1b,
                                            const float* __restrict__ c2w,
                                            const float* __restrict__ c2b,
                                            float* __restrict__ out, int out_size) {
    __shared__ float w_sh[NS];
    __shared__ float ra[NP];
    __shared__ float h_sh[128];
    __shared__ float cls[2];
    const int b = blockIdx.x;
    const int t = threadIdx.x;
    const int l = seqlen[b];
    int pe = ((l - 1 + 127) / 128) * 128;
    if (pe > NS) pe = NS;
    float nmask = (float)(NS - pe);
    for (int q = t; q < NS; q += 256)
        w_sh[q] = (g_wnum[b * NS + q] + nmask * g_base[q]) * (1.0f / NH);
    __syncthreads();

    float acc = 0.f;
    for (int q = 1; q < l - 1; q++)
        acc += w_sh[q] * g_rc[(size_t)(b * NS + q) * NP + t];
    ra[t] = acc;
    __syncthreads();

    if (t < 128) {
        float hv = c1b[t];
        for (int p = 0; p < NP; p++) hv += ra[p] * c1w[p * 128 + t];
        h_sh[t] = hv > 0.f ? hv : 0.01f * hv;
    }
    __syncthreads();
    if (t < 2) {
        float cv = c2b[t];
        for (int j = 0; j < 128; j++) cv += h_sh[j] * c2w[j * 2 + t];
        cls[t] = cv;
    }
    __syncthreads();
    if (t == 0) {
        float m  = fmaxf(cls[0], cls[1]);
        float e0 = __expf(cls[0] - m), e1 = __expf(cls[1] - m);
        float inv = 1.f / (e0 + e1);
        float p0 = e0 * inv, p1 = e1 * inv;
        out[2 * b]     = p0;
        out[2 * b + 1] = p1;
        if (out_size >= 2 * NB + NB)
            out[2 * NB + b] = (p1 > p0) ? 1.0f : 0.0f;
    }
}

// ---------------------------------------------------------------- launch
extern "C" void kernel_launch(void* const* d_in, const int* in_sizes, int n_in,
                              void* d_out, int out_size) {
    const float* x      = (const float*)d_in[0];
    const int*   seqlen = (const int*)  d_in[1];
    const float* proj_w = (const float*)d_in[2];
    const float* proj_b = (const float*)d_in[3];
    const float* conv_w = (const float*)d_in[4];
    const float* conv_b = (const float*)d_in[5];
    const float* attn_w = (const float*)d_in[6];
    const float* attn_b = (const float*)d_in[7];
    const float* c1_w   = (const float*)d_in[8];
    const float* c1_b   = (const float*)d_in[9];
    const float* c2_w   = (const float*)d_in[10];
    const float* c2_b   = (const float*)d_in[11];
    float* out = (float*)d_out;

    cudaFuncSetAttribute(k_pm,  cudaFuncAttributeMaxDynamicSharedMemorySize, SMEM_MMA);
    cudaFuncSetAttribute(k_cm,  cudaFuncAttributeMaxDynamicSharedMemorySize, SMEM_MMA);
    cudaFuncSetAttribute(k_ltm, cudaFuncAttributeMaxDynamicSharedMemorySize, SMEM_LT2);

    k_sx   <<<NM * NE / 1024, 256>>>(x);
    k_prep <<<2 * NP + NHS + 1, 256>>>(proj_w, conv_w, attn_w, attn_b);
    k_pm   <<<dim3(NP / 128, NM / 128), 256, SMEM_MMA>>>(proj_b);
    k_cm   <<<dim3(NP / 128, NS / 128, NB), 256, SMEM_MMA>>>(seqlen, conv_b);
    k_ltm  <<<dim3(NHS / 128, NB), 512, SMEM_LT2>>>(seqlen);
    k_w    <<<NB, 512>>>(seqlen);
    k_ra   <<<NB, 256>>>(seqlen, c1_w, c1_b, c2_w, c2_b, out, out_size);
}

// round 10
// speedup vs baseline: 2.7043x; 1.1151x over previous
#include <cuda_runtime.h>
#include <cuda_bf16.h>
#include <cstdint>

// Dims
#define NB 32
#define NS 512
#define NE 1024
#define NP 256
#define NH 8
#define NHS 4096      /* NH*NS */
#define NM 16384      /* NB*NS */
#define NKC 768       /* NP*3 conv reduction */

// Scratch (allowed: __device__ globals)
__device__ __align__(16) __nv_bfloat16 g_xH[(size_t)NM * NE];   // x hi
__device__ __align__(16) __nv_bfloat16 g_xL[(size_t)NM * NE];   // x lo
__device__ __align__(16) __nv_bfloat16 g_pwH[(size_t)NP * NE];  // proj_w^T hi [n][k]
__device__ __align__(16) __nv_bfloat16 g_pwL[(size_t)NP * NE];
__device__ __align__(16) __nv_bfloat16 g_pjH[(size_t)NM * NP];  // proj hi
__device__ __align__(16) __nv_bfloat16 g_pjL[(size_t)NM * NP];  // proj lo
__device__ __align__(16) __nv_bfloat16 g_WtH[(size_t)NP * NKC]; // conv_w^T hi [o][kk]
__device__ __align__(16) __nv_bfloat16 g_WtL[(size_t)NP * NKC];
__device__ __align__(16) float g_rc[(size_t)NM * NP];           // rep_conv fp32
__device__ __align__(16) __nv_bfloat16 g_rcH[(size_t)NM * NP];  // rep_conv hi
__device__ __align__(16) __nv_bfloat16 g_rcL[(size_t)NM * NP];  // rep_conv lo
__device__ __align__(16) __nv_bfloat16 g_BtH[(size_t)NHS * NP]; // attn_w^T reordered hi
__device__ __align__(16) __nv_bfloat16 g_BtL[(size_t)NHS * NP];
__device__ __align__(16) float g_A[(size_t)NB * NS * NS];       // head-folded exp
__device__ __align__(16) float g_abr[NHS];                      // reordered attn_b
__device__ __align__(16) float g_wnum[NB * NS];                 // softmax-weight numerator
__device__ __align__(16) float g_base[NS];                      // masked-row analytic contribution

// ================================================================ helpers
__device__ __forceinline__ uint32_t smem_to_u32(const void* p) {
    uint32_t a;
    asm("{ .reg .u64 t; cvta.to.shared.u64 t, %1; cvt.u32.u64 %0, t; }" : "=r"(a) : "l"(p));
    return a;
}
__device__ __forceinline__ void ldsm_x4(uint32_t* r, uint32_t addr) {
    asm volatile("ldmatrix.sync.aligned.m8n8.x4.shared.b16 {%0,%1,%2,%3}, [%4];"
                 : "=r"(r[0]), "=r"(r[1]), "=r"(r[2]), "=r"(r[3]) : "r"(addr));
}
__device__ __forceinline__ void mma_bf16(float* c, const uint32_t* a, const uint32_t* bb) {
    asm volatile(
        "mma.sync.aligned.m16n8k16.row.col.f32.bf16.bf16.f32 "
        "{%0,%1,%2,%3}, {%4,%5,%6,%7}, {%8,%9}, {%0,%1,%2,%3};"
        : "+f"(c[0]), "+f"(c[1]), "+f"(c[2]), "+f"(c[3])
        : "r"(a[0]), "r"(a[1]), "r"(a[2]), "r"(a[3]), "r"(bb[0]), "r"(bb[1]));
}
__device__ __forceinline__ void cp16(uint32_t smem, const void* g) {
    asm volatile("cp.async.ca.shared.global [%0], [%1], 16;" :: "r"(smem), "l"(g));
}
__device__ __forceinline__ void cp16z(uint32_t smem, const void* g, uint32_t sz) {
    asm volatile("cp.async.ca.shared.global [%0], [%1], 16, %2;" :: "r"(smem), "l"(g), "r"(sz));
}
#define CP_COMMIT() asm volatile("cp.async.commit_group;" ::: "memory")
#define CP_WAIT1()  asm volatile("cp.async.wait_group 1;" ::: "memory")
#define CP_WAIT0()  asm volatile("cp.async.wait_group 0;" ::: "memory")

__device__ __forceinline__ void split_store(__nv_bfloat16* pH, __nv_bfloat16* pL,
                                            float a, float b) {
    __nv_bfloat162 h, lo;
    h.x = __float2bfloat16(a); h.y = __float2bfloat16(b);
    lo.x = __float2bfloat16(a - __bfloat162float(h.x));
    lo.y = __float2bfloat16(b - __bfloat162float(h.y));
    *(__nv_bfloat162*)pH = h;
    *(__nv_bfloat162*)pL = lo;
}

// ---------------------------------------------------------------- prep kernels
// split x -> bf16 hi/lo
__global__ void k_sx(const float* __restrict__ x) {
    size_t idx = ((size_t)blockIdx.x * 256 + threadIdx.x) * 4;
    float4 v = *(const float4*)(x + idx);
    split_store(g_xH + idx,     g_xL + idx,     v.x, v.y);
    split_store(g_xH + idx + 2, g_xL + idx + 2, v.z, v.w);
}

// Combined prep: proj_w^T, conv_w^T, attn_w^T(reordered), base.
__global__ void k_prep(const float* __restrict__ pw, const float* __restrict__ cw,
                       const float* __restrict__ aw, const float* __restrict__ ab) {
    const int bid = blockIdx.x;
    if (bid < NP) {                        // proj_w [E,P] -> [P,E] hi/lo
        int o = bid;
        for (int k = threadIdx.x; k < NE; k += 256) {
            float v = pw[(size_t)k * NP + o];
            __nv_bfloat16 hi = __float2bfloat16(v);
            g_pwH[(size_t)o * NE + k] = hi;
            g_pwL[(size_t)o * NE + k] = __float2bfloat16(v - __bfloat162float(hi));
        }
    } else if (bid < 2 * NP) {             // conv_w [O,I,K3] -> [o][kk], kk=k*256+i
        int o = bid - NP;
        for (int kk = threadIdx.x; kk < NKC; kk += 256) {
            int i = kk & 255, k = kk >> 8;
            float v = cw[(size_t)o * NKC + i * 3 + k];
            __nv_bfloat16 hi = __float2bfloat16(v);
            g_WtH[(size_t)o * NKC + kk] = hi;
            g_WtL[(size_t)o * NKC + kk] = __float2bfloat16(v - __bfloat162float(hi));
        }
    } else if (bid < 2 * NP + NHS) {       // attn_w reorder+transpose, n' = q*8+h
        int np = bid - 2 * NP;
        int k  = threadIdx.x;
        int q = np >> 3, h = np & 7;
        float v = aw[(size_t)k * NHS + h * NS + q];
        __nv_bfloat16 hi = __float2bfloat16(v);
        g_BtH[(size_t)np * NP + k] = hi;
        g_BtL[(size_t)np * NP + k] = __float2bfloat16(v - __bfloat162float(hi));
        if (k == 0) g_abr[np] = ab[h * NS + q];
    } else {                               // base[q] = sum_h softmax(attn_b)[h*S+q]
        __shared__ float red[256];
        int t = threadIdx.x;
        float mx = -1e30f;
        for (int j = t; j < NHS; j += 256) mx = fmaxf(mx, ab[j]);
        red[t] = mx; __syncthreads();
        for (int s = 128; s; s >>= 1) { if (t < s) red[t] = fmaxf(red[t], red[t + s]); __syncthreads(); }
        mx = red[0]; __syncthreads();
        float sum = 0.f;
        for (int j = t; j < NHS; j += 256) sum += __expf(ab[j] - mx);
        red[t] = sum; __syncthreads();
        for (int s = 128; s; s >>= 1) { if (t < s) red[t] += red[t + s]; __syncthreads(); }
        float z0 = red[0];
        for (int q = t; q < NS; q += 256) {
            float acc = 0.f;
            for (int h = 0; h < NH; h++) acc += __expf(ab[h * NS + q] - mx);
            g_base[q] = acc / z0;
        }
    }
}

// ---------------------------------------------------------------- pipelined mma core (k_pm/k_cm)
// 128x128 block tile, 8 warps (4M x 2N), K chunks of 32, cp.async 3-stage,
// ONE __syncthreads per chunk (write target (kc+2)%3 never aliases live stages).
#define LDA2 40
#define T_BYTES (128 * LDA2 * 2)      /* 10240 per tile */
#define ST_BYTES (4 * T_BYTES)        /* AH AL BH BL per stage */
#define SMEM_MMA (3 * ST_BYTES + 512)

#define MMA_DECL                                                          \
    extern __shared__ char sm[];                                          \
    const uint32_t smb = smem_to_u32(sm);                                 \
    float* exS = (float*)(sm + 3 * ST_BYTES);                             \
    const int tid = threadIdx.x;                                          \
    const int lane = tid & 31, wid = tid >> 5;                            \
    const int wm = wid >> 1, wn = wid & 1;                                \
    const int g = lane >> 2, t = lane & 3;                                \
    float c[2][8][4];                                                     \
    _Pragma("unroll") for (int i = 0; i < 2; i++)                         \
    _Pragma("unroll") for (int j = 0; j < 8; j++)                         \
    _Pragma("unroll") for (int k = 0; k < 4; k++) c[i][j][k] = 0.f;       \
    const int aLOff = (lane & 15) * LDA2 + (lane >> 4) * 8;               \
    const int bLOff = ((lane & 7) + ((lane >> 4) * 8)) * LDA2 + ((lane >> 3) & 1) * 8;

#define MMA_COMPUTE(st_)                                                      \
    {                                                                         \
        const uint32_t base = smb + (uint32_t)((st_) * ST_BYTES);             \
        _Pragma("unroll")                                                     \
        for (int kk = 0; kk < 2; kk++) {                                      \
            const int k0 = kk * 16;                                           \
            uint32_t ah[2][4], al[2][4], bh[8][2], bl[8][2];                  \
            _Pragma("unroll")                                                 \
            for (int mt = 0; mt < 2; mt++) {                                  \
                uint32_t addr = base +                                        \
                    (uint32_t)(((wm * 32 + mt * 16) * LDA2 + k0 + aLOff) * 2);\
                ldsm_x4(ah[mt], addr);                                        \
                ldsm_x4(al[mt], addr + T_BYTES);                              \
            }                                                                 \
            _Pragma("unroll")                                                 \
            for (int np2 = 0; np2 < 4; np2++) {                               \
                uint32_t addr = base + 2 * T_BYTES +                          \
                    (uint32_t)(((wn * 64 + np2 * 16) * LDA2 + k0 + bLOff) * 2);\
                uint32_t r[4];                                                \
                ldsm_x4(r, addr);                                             \
                bh[np2 * 2][0] = r[0]; bh[np2 * 2][1] = r[1];                 \
                bh[np2 * 2 + 1][0] = r[2]; bh[np2 * 2 + 1][1] = r[3];         \
                ldsm_x4(r, addr + T_BYTES);                                   \
                bl[np2 * 2][0] = r[0]; bl[np2 * 2][1] = r[1];                 \
                bl[np2 * 2 + 1][0] = r[2]; bl[np2 * 2 + 1][1] = r[3];         \
            }                                                                 \
            _Pragma("unroll")                                                 \
            for (int mt = 0; mt < 2; mt++)                                    \
                _Pragma("unroll")                                             \
                for (int nt = 0; nt < 8; nt++) {                              \
                    mma_bf16(c[mt][nt], ah[mt], bh[nt]);                      \
                    mma_bf16(c[mt][nt], ah[mt], bl[nt]);                      \
                    mma_bf16(c[mt][nt], al[mt], bh[nt]);                      \
                }                                                             \
        }                                                                     \
    }

// ---------------------------------------------------------------- proj (mma)
__global__ void __launch_bounds__(256, 2) k_pm(const float* __restrict__ pb) {
    const int n0 = blockIdx.x * 128;
    const int m0 = blockIdx.y * 128;
    MMA_DECL
    if (tid < 128) exS[tid] = pb[n0 + tid];

#define PF_P(kc_, st_) do {                                                  \
    uint32_t sb = smb + (uint32_t)((st_) * ST_BYTES);                        \
    _Pragma("unroll") for (int i = 0; i < 2; i++) {                          \
        int idx = i * 256 + tid;                                             \
        int row = idx >> 2, col = (idx & 3) * 8;                             \
        uint32_t so = (uint32_t)((row * LDA2 + col) * 2);                    \
        size_t ga = (size_t)(m0 + row) * NE + (kc_) * 32 + col;              \
        size_t gb = (size_t)(n0 + row) * NE + (kc_) * 32 + col;              \
        cp16(sb + so,               g_xH + ga);                              \
        cp16(sb + T_BYTES + so,     g_xL + ga);                              \
        cp16(sb + 2 * T_BYTES + so, g_pwH + gb);                             \
        cp16(sb + 3 * T_BYTES + so, g_pwL + gb);                             \
    }                                                                        \
} while (0)

    PF_P(0, 0); CP_COMMIT();
    PF_P(1, 1); CP_COMMIT();
    for (int kc = 0; kc < 32; kc++) {
        if (kc < 31) CP_WAIT1(); else CP_WAIT0();
        __syncthreads();
        MMA_COMPUTE(kc % 3)
        if (kc + 2 < 32) { PF_P(kc + 2, (kc + 2) % 3); CP_COMMIT(); }
    }
#pragma unroll
    for (int mt = 0; mt < 2; mt++) {
        const int r0 = m0 + wm * 32 + mt * 16 + g;
#pragma unroll
        for (int nt = 0; nt < 8; nt++) {
            const int lc = wn * 64 + nt * 8 + 2 * t;
            const int col = n0 + lc;
            float b0 = exS[lc], b1 = exS[lc + 1];
            split_store(g_pjH + (size_t)r0 * NP + col, g_pjL + (size_t)r0 * NP + col,
                        c[mt][nt][0] + b0, c[mt][nt][1] + b1);
            split_store(g_pjH + (size_t)(r0 + 8) * NP + col, g_pjL + (size_t)(r0 + 8) * NP + col,
                        c[mt][nt][2] + b0, c[mt][nt][3] + b1);
        }
    }
}

// ---------------------------------------------------------------- conv (mma)
__global__ void __launch_bounds__(256, 2) k_cm(const int* __restrict__ seqlen,
                                               const float* __restrict__ cb) {
    const int n0 = blockIdx.x * 128;
    const int s0 = blockIdx.y * 128;
    const int b  = blockIdx.z;
    const int l  = seqlen[b];
    if (s0 >= l - 1) return;
    MMA_DECL
    if (tid < 128) exS[tid] = cb[n0 + tid];

#define PF_C(kc_, st_) do {                                                  \
    uint32_t sb = smb + (uint32_t)((st_) * ST_BYTES);                        \
    const int tap = (kc_) >> 3;                                              \
    const int i0 = ((kc_) & 7) * 32;                                         \
    _Pragma("unroll") for (int i = 0; i < 2; i++) {                          \
        int idx = i * 256 + tid;                                             \
        int row = idx >> 2, col = (idx & 3) * 8;                             \
        uint32_t so = (uint32_t)((row * LDA2 + col) * 2);                    \
        int srow = s0 + row + tap;                                           \
        uint32_t sz = (srow < NS) ? 16u : 0u;                                \
        int srcl = (srow < NS) ? srow : (NS - 1);                            \
        size_t ga = (size_t)(b * NS + srcl) * NP + i0 + col;                 \
        size_t gb = (size_t)(n0 + row) * NKC + (kc_) * 32 + col;             \
        cp16z(sb + so,           g_pjH + ga, sz);                            \
        cp16z(sb + T_BYTES + so, g_pjL + ga, sz);                            \
        cp16(sb + 2 * T_BYTES + so, g_WtH + gb);                             \
        cp16(sb + 3 * T_BYTES + so, g_WtL + gb);                             \
    }                                                                        \
} while (0)

    PF_C(0, 0); CP_COMMIT();
    PF_C(1, 1); CP_COMMIT();
    for (int kc = 0; kc < 24; kc++) {
        if (kc < 23) CP_WAIT1(); else CP_WAIT0();
        __syncthreads();
        MMA_COMPUTE(kc % 3)
        if (kc + 2 < 24) { PF_C(kc + 2, (kc + 2) % 3); CP_COMMIT(); }
    }
#pragma unroll
    for (int mt = 0; mt < 2; mt++) {
#pragma unroll
        for (int rr = 0; rr < 2; rr++) {
            const int s = s0 + wm * 32 + mt * 16 + rr * 8 + g;
            const bool valid = (s >= 1) && (s < l - 1);
            const size_t rowo = (size_t)(b * NS + s) * NP;
#pragma unroll
            for (int nt = 0; nt < 8; nt++) {
                const int lc = wn * 64 + nt * 8 + 2 * t;
                const int col = n0 + lc;
                float v0 = fmaxf(c[mt][nt][rr * 2 + 0] + exS[lc], 0.f);
                float v1 = fmaxf(c[mt][nt][rr * 2 + 1] + exS[lc + 1], 0.f);
                v0 = valid ? v0 : 0.f;
                v1 = valid ? v1 : 0.f;
                *(float2*)&g_rc[rowo + col] = make_float2(v0, v1);
                split_store(g_rcH + rowo + col, g_rcL + rowo + col, v0, v1);
            }
        }
    }
}

// ---------------------------------------------------------------- logits (resident-B mma)
// Grid (ntb, b), 512 threads = 16 warps (4M x 4N, warp tile 32x32).
// B (128 n' x 256 K, hi/lo) resident in smem; A streamed per s-tile, 3-stage.
#define LDB 264
#define B_TILE_B (128 * LDB * 2)          /* 67584 */
#define A_ST_B   (128 * LDA2 * 2)         /* 10240 per tile */
#define A_STAGE  (2 * A_ST_B)             /* hi+lo = 20480 */
#define OFF_A2   (2 * B_TILE_B)           /* 135168 */
#define OFF_EX2  (OFF_A2 + 3 * A_STAGE)   /* 196608 */
#define SMEM_LT2 (OFF_EX2 + 512)

__global__ void __launch_bounds__(512, 1) k_ltm(const int* __restrict__ seqlen) {
    const int ntb = blockIdx.x;
    const int b   = blockIdx.y;
    const int l   = seqlen[b];
    extern __shared__ char sm[];
    const uint32_t smb = smem_to_u32(sm);
    float* exS = (float*)(sm + OFF_EX2);
    const int tid = threadIdx.x;
    const int lane = tid & 31, wid = tid >> 5;
    const int wm = wid >> 2, wn = wid & 3;
    const int g = lane >> 2, t = lane & 3;

    if (tid < 128) exS[tid] = g_abr[ntb * 128 + tid];

    // Resident B load (hi+lo), 8192 cp16 over 512 threads.
#pragma unroll
    for (int i = 0; i < 8; i++) {
        int idx = i * 512 + tid;               // 4096 per tile
        int row = idx >> 5, col = (idx & 31) * 8;
        uint32_t so = (uint32_t)((row * LDB + col) * 2);
        size_t gb = (size_t)(ntb * 128 + row) * NP + col;
        cp16(smb + so,            g_BtH + gb);
        cp16(smb + B_TILE_B + so, g_BtL + gb);
    }
    CP_COMMIT();
    CP_WAIT0();               // B fully resident before mainloop
    __syncthreads();

    const int aLOff = (lane & 15) * LDA2 + (lane >> 4) * 8;
    const int bLOff = ((lane & 7) + ((lane >> 4) * 8)) * LDB + ((lane >> 3) & 1) * 8;

#define PF_A2(kc_, st_) do {                                                 \
    uint32_t sb = smb + OFF_A2 + (uint32_t)((st_) * A_STAGE);                \
    int row = tid >> 2, col = (tid & 3) * 8;                                 \
    uint32_t so = (uint32_t)((row * LDA2 + col) * 2);                        \
    size_t ga = (size_t)(b * NS + s0 + row) * NP + (kc_) * 32 + col;         \
    cp16(sb + so,          g_rcH + ga);                                      \
    cp16(sb + A_ST_B + so, g_rcL + ga);                                      \
} while (0)

    for (int s0 = 0; s0 < l - 1; s0 += 128) {
        float c[2][4][4];
#pragma unroll
        for (int i = 0; i < 2; i++)
#pragma unroll
            for (int j = 0; j < 4; j++)
#pragma unroll
                for (int k = 0; k < 4; k++) c[i][j][k] = 0.f;

        PF_A2(0, 0); CP_COMMIT();
        PF_A2(1, 1); CP_COMMIT();
        for (int kc = 0; kc < 8; kc++) {
            if (kc < 7) CP_WAIT1(); else CP_WAIT0();
            __syncthreads();
            const uint32_t abase = smb + OFF_A2 + (uint32_t)((kc % 3) * A_STAGE);
#pragma unroll
            for (int kk = 0; kk < 2; kk++) {
                const int k0 = kk * 16;
                const int kg = kc * 32 + k0;
                uint32_t ah[2][4], al[2][4], bh[4][2], bl[4][2];
#pragma unroll
                for (int mt = 0; mt < 2; mt++) {
                    uint32_t addr = abase +
                        (uint32_t)(((wm * 32 + mt * 16) * LDA2 + k0 + aLOff) * 2);
                    ldsm_x4(ah[mt], addr);
                    ldsm_x4(al[mt], addr + A_ST_B);
                }
#pragma unroll
                for (int np2 = 0; np2 < 2; np2++) {
                    uint32_t addr = smb +
                        (uint32_t)(((wn * 32 + np2 * 16) * LDB + kg + bLOff) * 2);
                    uint32_t r[4];
                    ldsm_x4(r, addr);
                    bh[np2 * 2][0] = r[0]; bh[np2 * 2][1] = r[1];
                    bh[np2 * 2 + 1][0] = r[2]; bh[np2 * 2 + 1][1] = r[3];
                    ldsm_x4(r, addr + B_TILE_B);
                    bl[np2 * 2][0] = r[0]; bl[np2 * 2][1] = r[1];
                    bl[np2 * 2 + 1][0] = r[2]; bl[np2 * 2 + 1][1] = r[3];
                }
#pragma unroll
                for (int mt = 0; mt < 2; mt++)
#pragma unroll
                    for (int nt = 0; nt < 4; nt++) {
                        mma_bf16(c[mt][nt], ah[mt], bh[nt]);
                        mma_bf16(c[mt][nt], ah[mt], bl[nt]);
                        mma_bf16(c[mt][nt], al[mt], bh[nt]);
                    }
            }
            if (kc + 2 < 8) { PF_A2(kc + 2, (kc + 2) % 3); CP_COMMIT(); }
        }

        // Epilogue: exp + head-fold (8 n' = 1 q per nt tile) -> g_A
        const int sr = b * NS + s0;
#pragma unroll
        for (int mt = 0; mt < 2; mt++) {
            const int r0 = wm * 32 + mt * 16 + g;
            const int r1 = r0 + 8;
#pragma unroll
            for (int nt = 0; nt < 4; nt++) {
                const int lc = wn * 32 + nt * 8 + 2 * t;
                float e00 = __expf(c[mt][nt][0] + exS[lc]);
                float e01 = __expf(c[mt][nt][1] + exS[lc + 1]);
                float e10 = __expf(c[mt][nt][2] + exS[lc]);
                float e11 = __expf(c[mt][nt][3] + exS[lc + 1]);
                float s0v = e00 + e01, s1v = e10 + e11;
                s0v += __shfl_xor_sync(0xFFFFFFFFu, s0v, 1);
                s0v += __shfl_xor_sync(0xFFFFFFFFu, s0v, 2);
                s1v += __shfl_xor_sync(0xFFFFFFFFu, s1v, 1);
                s1v += __shfl_xor_sync(0xFFFFFFFFu, s1v, 2);
                if (t == 0) {
                    const int q = ntb * 16 + wn * 4 + nt;
                    g_A[(size_t)(sr + r0) * NS + q] = s0v;
                    g_A[(size_t)(sr + r1) * NS + q] = s1v;
                }
            }
        }
        __syncthreads();   // A stages reused next s-tile; also orders epilogue vs prefetch
    }
}

// Z from row-sums of A, then wnum[b,q] = sum_s A[b,s,q]/Z[s]
__global__ void __launch_bounds__(512) k_w(const int* __restrict__ seqlen) {
    __shared__ float Zs[NS];
    const int b = blockIdx.x;
    const int tid = threadIdx.x;
    const int lane = tid & 31, w = tid >> 5;   // 16 warps
    const int l = seqlen[b];
    int pe = ((l - 1 + 127) >> 7) << 7;
    if (pe > NS) pe = NS;
    for (int s = w; s < pe; s += 16) {
        const float* row = g_A + (size_t)(b * NS + s) * NS;
        float acc = 0.f;
        for (int q = lane; q < NS; q += 32) acc += row[q];
#pragma unroll
        for (int o = 16; o; o >>= 1) acc += __shfl_xor_sync(0xFFFFFFFFu, acc, o);
        if (lane == 0) Zs[s] = 1.f / acc;
    }
    __syncthreads();
    for (int q = tid; q < NS; q += 512) {
        float acc = 0.f;
        size_t basei = (size_t)b * NS * NS + q;
#pragma unroll 4
        for (int s = 0; s < pe; s++)
            acc += g_A[basei + (size_t)s * NS] * Zs[s];
        g_wnum[b * NS + q] = acc;
    }
}

// Finalize: w, rep_attn, classifier, softmax, argmax -> out
__global__ void __launch_bounds__(256) k_ra(const int* __restrict__ seqlen,
                                            const float* __restrict__ c1w,
                                            const float* __restrict__ c1b,
                                            const float* __restrict__ c2w,
                                            const float* __restrict__ c2b,
                                            float* __restrict__ out, int out_size) {
    __shared__ float w_sh[NS];
    __shared__ float ra[NP];
    __shared__ float h_sh[128];
    __shared__ float cls[2];
    const int b = blockIdx.x;
    const int t = threadIdx.x;
    const int l = seqlen[b];
    int pe = ((l - 1 + 127) / 128) * 128;
    if (pe > NS) pe = NS;
    float nmask = (float)(NS - pe);
    for (int q = t; q < NS; q += 256)
        w_sh[q] = (g_wnum[b * NS + q] + nmask * g_base[q]) * (1.0f / NH);
    __syncthreads();

    float acc = 0.f;
    for (int q = 1; q < l - 1; q++)
        acc += w_sh[q] * g_rc[(size_t)(b * NS + q) * NP + t];
    ra[t] = acc;
    __syncthreads();

    if (t < 128) {
        float hv = c1b[t];
        for (int p = 0; p < NP; p++) hv += ra[p] * c1w[p * 128 + t];
        h_sh[t] = hv > 0.f ? hv : 0.01f * hv;
    }
    __syncthreads();
    if (t < 2) {
        float cv = c2b[t];
        for (int j = 0; j < 128; j++) cv += h_sh[j] * c2w[j * 2 + t];
        cls[t] = cv;
    }
    __syncthreads();
    if (t == 0) {
        float m  = fmaxf(cls[0], cls[1]);
        float e0 = __expf(cls[0] - m), e1 = __expf(cls[1] - m);
        float inv = 1.f / (e0 + e1);
        float p0 = e0 * inv, p1 = e1 * inv;
        out[2 * b]     = p0;
        out[2 * b + 1] = p1;
        if (out_size >= 2 * NB + NB)
            out[2 * NB + b] = (p1 > p0) ? 1.0f : 0.0f;
    }
}

// ---------------------------------------------------------------- launch
extern "C" void kernel_launch(void* const* d_in, const int* in_sizes, int n_in,
                              void* d_out, int out_size) {
    const float* x      = (const float*)d_in[0];
    const int*   seqlen = (const int*)  d_in[1];
    const float* proj_w = (const float*)d_in[2];
    const float* proj_b = (const float*)d_in[3];
    const float* conv_w = (const float*)d_in[4];
    const float* conv_b = (const float*)d_in[5];
    const float* attn_w = (const float*)d_in[6];
    const float* attn_b = (const float*)d_in[7];
    const float* c1_w   = (const float*)d_in[8];
    const float* c1_b   = (const float*)d_in[9];
    const float* c2_w   = (const float*)d_in[10];
    const float* c2_b   = (const float*)d_in[11];
    float* out = (float*)d_out;

    cudaFuncSetAttribute(k_pm,  cudaFuncAttributeMaxDynamicSharedMemorySize, SMEM_MMA);
    cudaFuncSetAttribute(k_cm,  cudaFuncAttributeMaxDynamicSharedMemorySize, SMEM_MMA);
    cudaFuncSetAttribute(k_ltm, cudaFuncAttributeMaxDynamicSharedMemorySize, SMEM_LT2);

    k_sx   <<<NM * NE / 1024, 256>>>(x);
    k_prep <<<2 * NP + NHS + 1, 256>>>(proj_w, conv_w, attn_w, attn_b);
    k_pm   <<<dim3(NP / 128, NM / 128), 256, SMEM_MMA>>>(proj_b);
    k_cm   <<<dim3(NP / 128, NS / 128, NB), 256, SMEM_MMA>>>(seqlen, conv_b);
    k_ltm  <<<dim3(NHS / 128, NB), 512, SMEM_LT2>>>(seqlen);
    k_w    <<<NB, 512>>>(seqlen);
    k_ra   <<<NB, 256>>>(seqlen, c1_w, c1_b, c2_w, c2_b, out, out_size);
}